// round 13
// baseline (speedup 1.0000x reference)
#include <cuda_runtime.h>
#include <cuda_bf16.h>
#include <cstdint>
#include <math.h>

#define BB 2
#define SS 2048
#define DD 1024
#define HH 16
#define HD 64
#define ROWS (BB*SS)

// Scratch (static device globals — no runtime allocation)
__device__ __nv_bfloat16 g_xn16[ROWS * DD];
__device__ __nv_bfloat16 g_qkv16[ROWS * 3 * DD];
__device__ __nv_bfloat16 g_ctx16[ROWS * DD];
__device__ __nv_bfloat16 g_w16[4 * DD * DD];   // bf16 wq,wk,wv,wo
__device__ float g_bqkv[3 * DD];

// ---------------------------------------------------------------------------
// helpers
// ---------------------------------------------------------------------------
__device__ __forceinline__ uint32_t smem_u32(const void* p) {
    uint32_t a;
    asm("{ .reg .u64 t; cvta.to.shared.u64 t, %1; cvt.u32.u64 %0, t; }"
        : "=r"(a) : "l"(p));
    return a;
}

// pack two fp32 -> bf16x2 (lo = first arg, hi = second), round-to-nearest
__device__ __forceinline__ uint32_t pack_bf16(float lo, float hi) {
    uint32_t d;
    asm("cvt.rn.bf16x2.f32 %0, %1, %2;" : "=r"(d) : "f"(hi), "f"(lo));
    return d;
}

#define CP_ASYNC16(smem_addr, gptr) \
    asm volatile("cp.async.cg.shared.global [%0], [%1], 16;" \
                 :: "r"(smem_addr), "l"(gptr) : "memory")
#define CP_COMMIT() asm volatile("cp.async.commit_group;" ::: "memory")
#define CP_WAIT(N)  asm volatile("cp.async.wait_group %0;" :: "n"(N) : "memory")

#define LDSM_X4(r0, r1, r2, r3, addr) \
    asm volatile("ldmatrix.sync.aligned.m8n8.x4.shared.b16 {%0,%1,%2,%3}, [%4];" \
                 : "=r"(r0), "=r"(r1), "=r"(r2), "=r"(r3) : "r"(addr))

__device__ __forceinline__ void mma_bf16(float* c, const uint32_t* a, const uint32_t* b) {
    asm volatile(
        "mma.sync.aligned.m16n8k16.row.col.f32.bf16.bf16.f32 "
        "{%0,%1,%2,%3}, {%4,%5,%6,%7}, {%8,%9}, {%0,%1,%2,%3};"
        : "+f"(c[0]), "+f"(c[1]), "+f"(c[2]), "+f"(c[3])
        : "r"(a[0]), "r"(a[1]), "r"(a[2]), "r"(a[3]), "r"(b[0]), "r"(b[1]));
}

// ---------------------------------------------------------------------------
// Weight prep: fp32 -> bf16 (rn) for all 4 weight matrices
// ---------------------------------------------------------------------------
__global__ void __launch_bounds__(256) wprep_kernel(
    const float* __restrict__ wq, const float* __restrict__ wk,
    const float* __restrict__ wv, const float* __restrict__ wo,
    __nv_bfloat16* __restrict__ dst)
{
    int i = blockIdx.x * 256 + threadIdx.x;        // float4 index
    const float* srcs[4] = {wq, wk, wv, wo};
    int which = i / (DD * DD / 4);
    int off   = i % (DD * DD / 4);
    float4 v = ((const float4*)srcs[which])[off];
    uint2 o;
    o.x = pack_bf16(v.x, v.y);
    o.y = pack_bf16(v.z, v.w);
    ((uint2*)dst)[i] = o;
}

__global__ void __launch_bounds__(256) bprep_kernel(
    const float* __restrict__ bq, const float* __restrict__ bk,
    const float* __restrict__ bv, float* __restrict__ dst)
{
    int i = blockIdx.x * 256 + threadIdx.x;        // 0..3071
    const float* s = (i < DD) ? bq : ((i < 2 * DD) ? bk : bv);
    dst[i] = s[i & (DD - 1)];
}

// ---------------------------------------------------------------------------
// LayerNorm: one block per row; output bf16
// ---------------------------------------------------------------------------
__global__ void __launch_bounds__(256) ln_kernel(
    const float* __restrict__ x, const float* __restrict__ gamma,
    const float* __restrict__ beta, __nv_bfloat16* __restrict__ out)
{
    int row = blockIdx.x;
    int t = threadIdx.x;
    float4 v = ((const float4*)(x + (size_t)row * DD))[t];
    float s  = v.x + v.y + v.z + v.w;
    float ss = v.x*v.x + v.y*v.y + v.z*v.z + v.w*v.w;

    #pragma unroll
    for (int o = 16; o; o >>= 1) {
        s  += __shfl_xor_sync(0xffffffffu, s,  o);
        ss += __shfl_xor_sync(0xffffffffu, ss, o);
    }
    __shared__ float rs[8], rss[8];
    int w = t >> 5;
    if ((t & 31) == 0) { rs[w] = s; rss[w] = ss; }
    __syncthreads();
    if (t < 32) {
        float a  = (t < 8) ? rs[t]  : 0.f;
        float aa = (t < 8) ? rss[t] : 0.f;
        #pragma unroll
        for (int o = 4; o; o >>= 1) {
            a  += __shfl_xor_sync(0xffffffffu, a,  o);
            aa += __shfl_xor_sync(0xffffffffu, aa, o);
        }
        if (t == 0) { rs[0] = a; rss[0] = aa; }
    }
    __syncthreads();
    float mean = rs[0] * (1.0f / DD);
    float var  = rss[0] * (1.0f / DD) - mean * mean;
    float rstd = rsqrtf(var + 1e-12f);

    float4 g  = ((const float4*)gamma)[t];
    float4 bt = ((const float4*)beta)[t];
    uint2 o;
    o.x = pack_bf16((v.x - mean) * rstd * g.x + bt.x,
                    (v.y - mean) * rstd * g.y + bt.y);
    o.y = pack_bf16((v.z - mean) * rstd * g.z + bt.z,
                    (v.w - mean) * rstd * g.w + bt.w);
    ((uint2*)(out + (size_t)row * DD))[t] = o;
}

// ---------------------------------------------------------------------------
// bf16 mma.sync GEMM-NT with ldmatrix fragment loads.
// Block 128x256, 8 warps (2x4) of 64x64. 3-stage cp.async, dynamic smem.
// ---------------------------------------------------------------------------
#define SKW 20
#define GSTG 3
#define GA_STAGE (128 * SKW)
#define GB_STAGE (256 * SKW)
#define GSMEM_BYTES (GSTG * (GA_STAGE + GB_STAGE) * 4)
#define KP (DD / 2)            // 512 pairs per row

template<bool OUT_BF16>
__global__ void __launch_bounds__(256) gemm_mma(
    const uint32_t* __restrict__ A, const uint32_t* __restrict__ W,
    const float* __restrict__ bias, const float* __restrict__ resid,
    void* __restrict__ Cout, int ldc)
{
    extern __shared__ __align__(16) uint32_t gsm[];
    uint32_t* sAb = gsm;
    uint32_t* sBb = gsm + GSTG * GA_STAGE;

    int tid  = threadIdx.x;
    int lane = tid & 31;
    int wid  = tid >> 5;
    int wm = (wid & 1) * 64;
    int wn = (wid >> 1) * 64;
    int rowBase = blockIdx.y * 128;
    int colBase = blockIdx.x * 256;
    int gid = lane >> 2;
    int tig = lane & 3;

    // ldmatrix lane->address components (in pairs)
    int a_row = lane & 15;                         // A: matrix row select
    int a_k4  = (lane >> 4) * 4;                   // A: 0 / +4 pairs (k+8 elems)
    int b_row = ((lane >> 4) & 1) * 8 + (lane & 7);// B: n-row within 16-row pair
    int b_k4  = ((lane >> 3) & 1) * 4;             // B: 0 / +4 pairs

    int lrow = tid >> 2;          // 0..63
    int lc4  = tid & 3;           // 0..3 (16B = 4 pairs each)
    const uint32_t* gA0 = A + (size_t)(rowBase + lrow) * KP + lc4 * 4;
    const uint32_t* gA1 = gA0 + (size_t)64 * KP;
    const uint32_t* gB0 = W + (size_t)(colBase + lrow) * KP + lc4 * 4;
    const uint32_t* gB1 = gB0 + (size_t)64 * KP;
    const uint32_t* gB2 = gB0 + (size_t)128 * KP;
    const uint32_t* gB3 = gB0 + (size_t)192 * KP;

    uint32_t offR0 = (uint32_t)((lrow * SKW + lc4 * 4) * 4);
    uint32_t offR1 = (uint32_t)(((lrow + 64) * SKW + lc4 * 4) * 4);

    uint32_t sawA[GSTG], sawB[GSTG];
    #pragma unroll
    for (int s = 0; s < GSTG; s++) {
        sawA[s] = smem_u32(sAb + s * GA_STAGE);
        sawB[s] = smem_u32(sBb + s * GB_STAGE);
    }

    float acc[4][8][4];
    #pragma unroll
    for (int mt = 0; mt < 4; mt++)
        #pragma unroll
        for (int nt = 0; nt < 8; nt++)
            #pragma unroll
            for (int r = 0; r < 4; r++) acc[mt][nt][r] = 0.f;

    const int NCHUNK = KP / 16;   // 32

    #pragma unroll
    for (int p = 0; p < 2; p++) {
        int k0 = p * 16;
        CP_ASYNC16(sawA[p] + offR0, gA0 + k0);
        CP_ASYNC16(sawA[p] + offR1, gA1 + k0);
        CP_ASYNC16(sawB[p] + offR0, gB0 + k0);
        CP_ASYNC16(sawB[p] + offR1, gB1 + k0);
        CP_ASYNC16(sawB[p] + offR0 + 128 * SKW * 4, gB2 + k0);
        CP_ASYNC16(sawB[p] + offR1 + 128 * SKW * 4, gB3 + k0);
        CP_COMMIT();
    }

    for (int c = 0; c < NCHUNK; c++) {
        if (c + 2 < NCHUNK) {
            int s = (c + 2) % GSTG;
            int k0 = (c + 2) * 16;
            CP_ASYNC16(sawA[s] + offR0, gA0 + k0);
            CP_ASYNC16(sawA[s] + offR1, gA1 + k0);
            CP_ASYNC16(sawB[s] + offR0, gB0 + k0);
            CP_ASYNC16(sawB[s] + offR1, gB1 + k0);
            CP_ASYNC16(sawB[s] + offR0 + 128 * SKW * 4, gB2 + k0);
            CP_ASYNC16(sawB[s] + offR1 + 128 * SKW * 4, gB3 + k0);
        }
        CP_COMMIT();
        CP_WAIT(2);
        __syncthreads();

        uint32_t paw = sawA[c % GSTG];
        uint32_t pbw = sawB[c % GSTG];
        #pragma unroll
        for (int ks = 0; ks < 2; ks++) {
            uint32_t kbyte = (uint32_t)(ks * 8 * 4);
            uint32_t af[4][4];
            #pragma unroll
            for (int mt = 0; mt < 4; mt++) {
                uint32_t ad = paw + ((wm + mt * 16 + a_row) * SKW + a_k4) * 4 + kbyte;
                LDSM_X4(af[mt][0], af[mt][1], af[mt][2], af[mt][3], ad);
            }
            uint32_t bf[8][2];
            #pragma unroll
            for (int j = 0; j < 4; j++) {
                uint32_t bd = pbw + ((wn + j * 16 + b_row) * SKW + b_k4) * 4 + kbyte;
                LDSM_X4(bf[2 * j][0], bf[2 * j][1], bf[2 * j + 1][0], bf[2 * j + 1][1], bd);
            }
            #pragma unroll
            for (int mt = 0; mt < 4; mt++)
                #pragma unroll
                for (int nt = 0; nt < 8; nt++)
                    mma_bf16(acc[mt][nt], af[mt], bf[nt]);
        }
        __syncthreads();
    }

    #pragma unroll
    for (int mt = 0; mt < 4; mt++) {
        int r0 = rowBase + wm + mt * 16 + gid;
        #pragma unroll
        for (int nt = 0; nt < 8; nt++) {
            int col = colBase + wn + nt * 8 + tig * 2;
            float2 b2 = *(const float2*)(bias + col);
            float o00 = acc[mt][nt][0] + b2.x, o01 = acc[mt][nt][1] + b2.y;
            float o10 = acc[mt][nt][2] + b2.x, o11 = acc[mt][nt][3] + b2.y;
            if (OUT_BF16) {
                __nv_bfloat16* C16 = (__nv_bfloat16*)Cout;
                *(uint32_t*)(C16 + (size_t)r0 * ldc + col)       = pack_bf16(o00, o01);
                *(uint32_t*)(C16 + (size_t)(r0 + 8) * ldc + col) = pack_bf16(o10, o11);
            } else {
                float* C = (float*)Cout;
                float2 r0v = *(const float2*)(resid + (size_t)r0 * ldc + col);
                float2 r1v = *(const float2*)(resid + (size_t)(r0 + 8) * ldc + col);
                float2 w0 = {o00 + r0v.x, o01 + r0v.y};
                float2 w1 = {o10 + r1v.x, o11 + r1v.y};
                *(float2*)(C + (size_t)r0 * ldc + col)       = w0;
                *(float2*)(C + (size_t)(r0 + 8) * ldc + col) = w1;
            }
        }
    }
}

// ---------------------------------------------------------------------------
// bf16 tensor-core flash attention with ldmatrix fragment loads.
// 128 q-rows/CTA, 64 keys/tile, 256 threads = 8 warps x 16 q-rows.
// ---------------------------------------------------------------------------
#define QSTR 36    // pair stride
#define QKVP (3 * DD / 2)   // 1536 pairs per qkv row

__global__ void __launch_bounds__(256) attn_mma(const float* __restrict__ mask)
{
    extern __shared__ __align__(16) uint32_t sm[];
    uint32_t* Qs  = sm;                     // 128 rows x 36 pairs
    uint32_t* Ks  = Qs + 128 * QSTR;        // 64 rows x 36
    uint32_t* Vt  = Ks + 64 * QSTR;         // 64 dims x 36 (keypairs)
    float*    Msk = (float*)(Vt + 64 * QSTR);  // 64

    int t = threadIdx.x;
    int lane = t & 31, wid = t >> 5;
    int gid = lane >> 2, tig = lane & 3;
    int b = blockIdx.z, h = blockIdx.y, qt = blockIdx.x;
    int qrow0 = b * SS + qt * 128;
    int qr = wid * 16;

    int a_row = lane & 15;
    int a_k4  = (lane >> 4) * 4;
    int b_row = ((lane >> 4) & 1) * 8 + (lane & 7);
    int b_k4  = ((lane >> 3) & 1) * 4;

    uint32_t sawQ = smem_u32(Qs);
    uint32_t sawK = smem_u32(Ks);
    uint32_t sawV = smem_u32(Vt);

    const uint32_t* qkvp = (const uint32_t*)g_qkv16;
    const uint32_t* qbase = qkvp + (size_t)qrow0 * QKVP + h * (HD / 2);

    // stage Q: 128 rows x 32 pairs = 1024 uint4 (4 pairs each)
    #pragma unroll
    for (int i = 0; i < 4; i++) {
        int idx = t + i * 256;
        int r = idx >> 3, q8 = idx & 7;
        *(uint4*)(Qs + r * QSTR + q8 * 4) =
            *(const uint4*)(qbase + (size_t)r * QKVP + q8 * 4);
    }

    float oacc[8][4];
    #pragma unroll
    for (int nd = 0; nd < 8; nd++)
        #pragma unroll
        for (int r = 0; r < 4; r++) oacc[nd][r] = 0.f;
    float mrow[2] = {-1e30f, -1e30f};
    float lrow[2] = {0.f, 0.f};

    for (int kt = 0; kt < SS / 64; kt++) {
        __syncthreads();
        const uint32_t* kbg = qkvp + (size_t)(b * SS + kt * 64) * QKVP
                              + (DD / 2) + h * (HD / 2);
        const uint32_t* vbg = kbg + (DD / 2);
        // K: 64 rows x 32 pairs = 512 uint4
        #pragma unroll
        for (int i = 0; i < 2; i++) {
            int idx = t + i * 256;
            int r = idx >> 3, q8 = idx & 7;
            *(uint4*)(Ks + r * QSTR + q8 * 4) =
                *(const uint4*)(kbg + (size_t)r * QKVP + q8 * 4);
        }
        // V transposed: read uint4 (= 8 dims) of one key, scatter to Vt[dim][key]
        __nv_bfloat16* vt16 = (__nv_bfloat16*)Vt;
        #pragma unroll
        for (int i = 0; i < 2; i++) {
            int idx = t + i * 256;
            int key = idx >> 3, d8 = idx & 7;
            uint4 vv = *(const uint4*)(vbg + (size_t)key * QKVP + d8 * 4);
            const uint32_t* vp = (const uint32_t*)&vv;
            #pragma unroll
            for (int p = 0; p < 4; p++) {
                __nv_bfloat162 pr = *(__nv_bfloat162*)&vp[p];
                int dim = d8 * 8 + p * 2;
                vt16[(size_t)dim * (QSTR * 2) + key]       = pr.x;
                vt16[(size_t)(dim + 1) * (QSTR * 2) + key] = pr.y;
            }
        }
        if (t < 64) Msk[t] = mask[b * SS + kt * 64 + t];
        __syncthreads();

        // ---- S = Q K^T (bf16 m16n8k16, ldmatrix) ----
        float sacc[8][4];
        #pragma unroll
        for (int nt = 0; nt < 8; nt++)
            #pragma unroll
            for (int r = 0; r < 4; r++) sacc[nt][r] = 0.f;

        #pragma unroll
        for (int ks = 0; ks < 4; ks++) {       // 4 k16 steps over 32 pairs
            uint32_t kbyte = (uint32_t)(ks * 8 * 4);
            uint32_t qa[4];
            {
                uint32_t ad = sawQ + ((qr + a_row) * QSTR + a_k4) * 4 + kbyte;
                LDSM_X4(qa[0], qa[1], qa[2], qa[3], ad);
            }
            uint32_t kf[8][2];
            #pragma unroll
            for (int j = 0; j < 4; j++) {
                uint32_t kd = sawK + ((j * 16 + b_row) * QSTR + b_k4) * 4 + kbyte;
                LDSM_X4(kf[2 * j][0], kf[2 * j][1], kf[2 * j + 1][0], kf[2 * j + 1][1], kd);
            }
            #pragma unroll
            for (int nt = 0; nt < 8; nt++)
                mma_bf16(sacc[nt], qa, kf[nt]);
        }

        // ---- online softmax (fp32, C-fragment layout) ----
        {
            float mx0 = mrow[0], mx1 = mrow[1];
            #pragma unroll
            for (int nt = 0; nt < 8; nt++) {
                float mk0 = Msk[nt * 8 + 2 * tig];
                float mk1 = Msk[nt * 8 + 2 * tig + 1];
                float* s = sacc[nt];
                s[0] = s[0] * 0.125f + mk0;
                s[1] = s[1] * 0.125f + mk1;
                s[2] = s[2] * 0.125f + mk0;
                s[3] = s[3] * 0.125f + mk1;
                mx0 = fmaxf(mx0, fmaxf(s[0], s[1]));
                mx1 = fmaxf(mx1, fmaxf(s[2], s[3]));
            }
            mx0 = fmaxf(mx0, __shfl_xor_sync(0xffffffffu, mx0, 1));
            mx0 = fmaxf(mx0, __shfl_xor_sync(0xffffffffu, mx0, 2));
            mx1 = fmaxf(mx1, __shfl_xor_sync(0xffffffffu, mx1, 1));
            mx1 = fmaxf(mx1, __shfl_xor_sync(0xffffffffu, mx1, 2));
            float c0 = __expf(mrow[0] - mx0);
            float c1 = __expf(mrow[1] - mx1);
            mrow[0] = mx0; mrow[1] = mx1;
            float ls0 = 0.f, ls1 = 0.f;
            #pragma unroll
            for (int nt = 0; nt < 8; nt++) {
                float* s = sacc[nt];
                s[0] = __expf(s[0] - mx0);
                s[1] = __expf(s[1] - mx0);
                s[2] = __expf(s[2] - mx1);
                s[3] = __expf(s[3] - mx1);
                ls0 += s[0] + s[1];
                ls1 += s[2] + s[3];
            }
            ls0 += __shfl_xor_sync(0xffffffffu, ls0, 1);
            ls0 += __shfl_xor_sync(0xffffffffu, ls0, 2);
            ls1 += __shfl_xor_sync(0xffffffffu, ls1, 1);
            ls1 += __shfl_xor_sync(0xffffffffu, ls1, 2);
            lrow[0] = lrow[0] * c0 + ls0;
            lrow[1] = lrow[1] * c1 + ls1;
            #pragma unroll
            for (int nd = 0; nd < 8; nd++) {
                float* o = oacc[nd];
                o[0] *= c0; o[1] *= c0; o[2] *= c1; o[3] *= c1;
            }
        }

        // ---- O += P V : pack P from C-fragments, V frags via ldmatrix ----
        #pragma unroll
        for (int j = 0; j < 4; j++) {          // 4 k16 blocks of 16 keys
            uint32_t pa[4];
            float* s0 = sacc[2 * j];
            float* s1 = sacc[2 * j + 1];
            pa[0] = pack_bf16(s0[0], s0[1]);   // row g,   keypair tig
            pa[1] = pack_bf16(s0[2], s0[3]);   // row g+8, keypair tig
            pa[2] = pack_bf16(s1[0], s1[1]);   // row g,   keypair tig+4
            pa[3] = pack_bf16(s1[2], s1[3]);   // row g+8, keypair tig+4
            uint32_t vbf[8][2];
            #pragma unroll
            for (int jj = 0; jj < 4; jj++) {
                uint32_t vd = sawV + ((jj * 16 + b_row) * QSTR + j * 8 + b_k4) * 4;
                LDSM_X4(vbf[2 * jj][0], vbf[2 * jj][1],
                        vbf[2 * jj + 1][0], vbf[2 * jj + 1][1], vd);
            }
            #pragma unroll
            for (int nd = 0; nd < 8; nd++)
                mma_bf16(oacc[nd], pa, vbf[nd]);
        }
    }

    // ---- epilogue: normalize, store ctx as bf16 ----
    {
        float inv0 = 1.f / lrow[0];
        float inv1 = 1.f / lrow[1];
        int r0 = qrow0 + qr + gid;
        #pragma unroll
        for (int nd = 0; nd < 8; nd++) {
            int col = h * HD + nd * 8 + 2 * tig;
            *(uint32_t*)(g_ctx16 + (size_t)r0 * DD + col) =
                pack_bf16(oacc[nd][0] * inv0, oacc[nd][1] * inv0);
            *(uint32_t*)(g_ctx16 + (size_t)(r0 + 8) * DD + col) =
                pack_bf16(oacc[nd][2] * inv1, oacc[nd][3] * inv1);
        }
    }
}

// ---------------------------------------------------------------------------
// Launcher
// ---------------------------------------------------------------------------
extern "C" void kernel_launch(void* const* d_in, const int* in_sizes, int n_in,
                              void* d_out, int out_size)
{
    const float* hidden = (const float*)d_in[0];
    const float* mask   = (const float*)d_in[1];
    const float* gamma  = (const float*)d_in[2];
    const float* beta   = (const float*)d_in[3];
    const float* wq = (const float*)d_in[4];
    const float* bq = (const float*)d_in[5];
    const float* wk = (const float*)d_in[6];
    const float* bk = (const float*)d_in[7];
    const float* wv = (const float*)d_in[8];
    const float* bv = (const float*)d_in[9];
    const float* wo = (const float*)d_in[10];
    const float* bo = (const float*)d_in[11];
    float* out = (float*)d_out;

    void *p_xn, *p_qkv, *p_ctx, *p_w, *p_bqkv;
    cudaGetSymbolAddress(&p_xn,  g_xn16);
    cudaGetSymbolAddress(&p_qkv, g_qkv16);
    cudaGetSymbolAddress(&p_ctx, g_ctx16);
    cudaGetSymbolAddress(&p_w,   g_w16);
    cudaGetSymbolAddress(&p_bqkv, g_bqkv);
    __nv_bfloat16* xn  = (__nv_bfloat16*)p_xn;
    __nv_bfloat16* qkv = (__nv_bfloat16*)p_qkv;
    __nv_bfloat16* ctx = (__nv_bfloat16*)p_ctx;
    __nv_bfloat16* w16 = (__nv_bfloat16*)p_w;
    float* bqkv = (float*)p_bqkv;

    // 0. Prep: bf16 weights, concat qkv bias
    wprep_kernel<<<4 * DD * DD / 4 / 256, 256>>>(wq, wk, wv, wo, w16);
    bprep_kernel<<<3 * DD / 256, 256>>>(bq, bk, bv, bqkv);

    // 1. LayerNorm (bf16 output)
    ln_kernel<<<ROWS, 256>>>(hidden, gamma, beta, xn);

    // 2. Fused QKV projection: [4096,1024] @ [3072,1024]^T -> bf16
    cudaFuncSetAttribute(gemm_mma<true>,
                         cudaFuncAttributeMaxDynamicSharedMemorySize, GSMEM_BYTES);
    cudaFuncSetAttribute(gemm_mma<false>,
                         cudaFuncAttributeMaxDynamicSharedMemorySize, GSMEM_BYTES);
    gemm_mma<true><<<dim3(3 * DD / 256, ROWS / 128), 256, GSMEM_BYTES>>>(
        (const uint32_t*)xn, (const uint32_t*)w16, bqkv, nullptr, qkv, 3 * DD);

    // 3. bf16 tensor-core flash attention
    int smem = (128 * QSTR + 64 * QSTR * 2) * 4 + 64 * 4;
    cudaFuncSetAttribute(attn_mma, cudaFuncAttributeMaxDynamicSharedMemorySize, smem);
    attn_mma<<<dim3(SS / 128, HH, BB), 256, smem>>>(mask);

    // 4. Output projection + bias + residual (fp32 out)
    gemm_mma<false><<<dim3(DD / 256, ROWS / 128), 256, GSMEM_BYTES>>>(
        (const uint32_t*)ctx, (const uint32_t*)(w16 + (size_t)3 * DD * DD),
        bo, hidden, out, DD);
}

// round 15
// speedup vs baseline: 1.0690x; 1.0690x over previous
#include <cuda_runtime.h>
#include <cuda_bf16.h>
#include <cstdint>
#include <math.h>

#define BB 2
#define SS 2048
#define DD 1024
#define HH 16
#define HD 64
#define ROWS (BB*SS)

// Scratch (static device globals — no runtime allocation)
__device__ __nv_bfloat16 g_xn16[ROWS * DD];
__device__ __nv_bfloat16 g_qkv16[ROWS * 3 * DD];
__device__ __nv_bfloat16 g_ctx16[ROWS * DD];
__device__ __nv_bfloat16 g_w16[4 * DD * DD];   // bf16 wq,wk,wv,wo
__device__ float g_bqkv[3 * DD];

// ---------------------------------------------------------------------------
// helpers
// ---------------------------------------------------------------------------
__device__ __forceinline__ uint32_t smem_u32(const void* p) {
    uint32_t a;
    asm("{ .reg .u64 t; cvta.to.shared.u64 t, %1; cvt.u32.u64 %0, t; }"
        : "=r"(a) : "l"(p));
    return a;
}

// pack two fp32 -> bf16x2 (lo = first arg, hi = second), round-to-nearest
__device__ __forceinline__ uint32_t pack_bf16(float lo, float hi) {
    uint32_t d;
    asm("cvt.rn.bf16x2.f32 %0, %1, %2;" : "=r"(d) : "f"(hi), "f"(lo));
    return d;
}

#define CP_ASYNC16(smem_addr, gptr) \
    asm volatile("cp.async.cg.shared.global [%0], [%1], 16;" \
                 :: "r"(smem_addr), "l"(gptr) : "memory")
#define CP_COMMIT() asm volatile("cp.async.commit_group;" ::: "memory")
#define CP_WAIT(N)  asm volatile("cp.async.wait_group %0;" :: "n"(N) : "memory")

#define LDSM_X4(r0, r1, r2, r3, addr) \
    asm volatile("ldmatrix.sync.aligned.m8n8.x4.shared.b16 {%0,%1,%2,%3}, [%4];" \
                 : "=r"(r0), "=r"(r1), "=r"(r2), "=r"(r3) : "r"(addr))

__device__ __forceinline__ void mma_bf16(float* c, const uint32_t* a, const uint32_t* b) {
    asm volatile(
        "mma.sync.aligned.m16n8k16.row.col.f32.bf16.bf16.f32 "
        "{%0,%1,%2,%3}, {%4,%5,%6,%7}, {%8,%9}, {%0,%1,%2,%3};"
        : "+f"(c[0]), "+f"(c[1]), "+f"(c[2]), "+f"(c[3])
        : "r"(a[0]), "r"(a[1]), "r"(a[2]), "r"(a[3]), "r"(b[0]), "r"(b[1]));
}

// ---------------------------------------------------------------------------
// Weight prep: fp32 -> bf16 (rn) for all 4 weight matrices
// ---------------------------------------------------------------------------
__global__ void __launch_bounds__(256) wprep_kernel(
    const float* __restrict__ wq, const float* __restrict__ wk,
    const float* __restrict__ wv, const float* __restrict__ wo,
    __nv_bfloat16* __restrict__ dst)
{
    int i = blockIdx.x * 256 + threadIdx.x;        // float4 index
    const float* srcs[4] = {wq, wk, wv, wo};
    int which = i / (DD * DD / 4);
    int off   = i % (DD * DD / 4);
    float4 v = ((const float4*)srcs[which])[off];
    uint2 o;
    o.x = pack_bf16(v.x, v.y);
    o.y = pack_bf16(v.z, v.w);
    ((uint2*)dst)[i] = o;
}

__global__ void __launch_bounds__(256) bprep_kernel(
    const float* __restrict__ bq, const float* __restrict__ bk,
    const float* __restrict__ bv, float* __restrict__ dst)
{
    int i = blockIdx.x * 256 + threadIdx.x;        // 0..3071
    const float* s = (i < DD) ? bq : ((i < 2 * DD) ? bk : bv);
    dst[i] = s[i & (DD - 1)];
}

// ---------------------------------------------------------------------------
// LayerNorm: one block per row; output bf16
// ---------------------------------------------------------------------------
__global__ void __launch_bounds__(256) ln_kernel(
    const float* __restrict__ x, const float* __restrict__ gamma,
    const float* __restrict__ beta, __nv_bfloat16* __restrict__ out)
{
    int row = blockIdx.x;
    int t = threadIdx.x;
    float4 v = ((const float4*)(x + (size_t)row * DD))[t];
    float s  = v.x + v.y + v.z + v.w;
    float ss = v.x*v.x + v.y*v.y + v.z*v.z + v.w*v.w;

    #pragma unroll
    for (int o = 16; o; o >>= 1) {
        s  += __shfl_xor_sync(0xffffffffu, s,  o);
        ss += __shfl_xor_sync(0xffffffffu, ss, o);
    }
    __shared__ float rs[8], rss[8];
    int w = t >> 5;
    if ((t & 31) == 0) { rs[w] = s; rss[w] = ss; }
    __syncthreads();
    if (t < 32) {
        float a  = (t < 8) ? rs[t]  : 0.f;
        float aa = (t < 8) ? rss[t] : 0.f;
        #pragma unroll
        for (int o = 4; o; o >>= 1) {
            a  += __shfl_xor_sync(0xffffffffu, a,  o);
            aa += __shfl_xor_sync(0xffffffffu, aa, o);
        }
        if (t == 0) { rs[0] = a; rss[0] = aa; }
    }
    __syncthreads();
    float mean = rs[0] * (1.0f / DD);
    float var  = rss[0] * (1.0f / DD) - mean * mean;
    float rstd = rsqrtf(var + 1e-12f);

    float4 g  = ((const float4*)gamma)[t];
    float4 bt = ((const float4*)beta)[t];
    uint2 o;
    o.x = pack_bf16((v.x - mean) * rstd * g.x + bt.x,
                    (v.y - mean) * rstd * g.y + bt.y);
    o.y = pack_bf16((v.z - mean) * rstd * g.z + bt.z,
                    (v.w - mean) * rstd * g.w + bt.w);
    ((uint2*)(out + (size_t)row * DD))[t] = o;
}

// ---------------------------------------------------------------------------
// bf16 mma.sync GEMM-NT, 2-CTA/SM occupancy version.
// Block 128x128, 8 warps (4x2) of 32x64. 3-stage cp.async, dynamic smem.
// ---------------------------------------------------------------------------
#define SKW 20
#define GSTG 3
#define GA_STAGE (128 * SKW)
#define GB_STAGE (128 * SKW)
#define GSMEM_BYTES (GSTG * (GA_STAGE + GB_STAGE) * 4)
#define KP (DD / 2)            // 512 pairs per row

template<bool OUT_BF16>
__global__ void __launch_bounds__(256, 2) gemm_mma(
    const uint32_t* __restrict__ A, const uint32_t* __restrict__ W,
    const float* __restrict__ bias, const float* __restrict__ resid,
    void* __restrict__ Cout, int ldc)
{
    extern __shared__ __align__(16) uint32_t gsm[];
    uint32_t* sAb = gsm;
    uint32_t* sBb = gsm + GSTG * GA_STAGE;

    int tid  = threadIdx.x;
    int lane = tid & 31;
    int wid  = tid >> 5;
    int wm = (wid & 3) * 32;       // 4 warp-rows of 32
    int wn = (wid >> 2) * 64;      // 2 warp-cols of 64
    int rowBase = blockIdx.y * 128;
    int colBase = blockIdx.x * 128;
    int gid = lane >> 2;
    int tig = lane & 3;

    // ldmatrix lane->address components (in pairs)
    int a_row = lane & 15;                         // A: matrix row select
    int a_k4  = (lane >> 4) * 4;                   // A: 0 / +4 pairs (k+8 elems)
    int b_row = ((lane >> 4) & 1) * 8 + (lane & 7);// B: n-row within 16-row pair
    int b_k4  = ((lane >> 3) & 1) * 4;             // B: 0 / +4 pairs

    int lrow = tid >> 2;          // 0..63
    int lc4  = tid & 3;           // 0..3 (16B = 4 pairs each)
    const uint32_t* gA0 = A + (size_t)(rowBase + lrow) * KP + lc4 * 4;
    const uint32_t* gA1 = gA0 + (size_t)64 * KP;
    const uint32_t* gB0 = W + (size_t)(colBase + lrow) * KP + lc4 * 4;
    const uint32_t* gB1 = gB0 + (size_t)64 * KP;

    uint32_t offR0 = (uint32_t)((lrow * SKW + lc4 * 4) * 4);
    uint32_t offR1 = (uint32_t)(((lrow + 64) * SKW + lc4 * 4) * 4);

    uint32_t sawA[GSTG], sawB[GSTG];
    #pragma unroll
    for (int s = 0; s < GSTG; s++) {
        sawA[s] = smem_u32(sAb + s * GA_STAGE);
        sawB[s] = smem_u32(sBb + s * GB_STAGE);
    }

    float acc[2][8][4];
    #pragma unroll
    for (int mt = 0; mt < 2; mt++)
        #pragma unroll
        for (int nt = 0; nt < 8; nt++)
            #pragma unroll
            for (int r = 0; r < 4; r++) acc[mt][nt][r] = 0.f;

    const int NCHUNK = KP / 16;   // 32

    #pragma unroll
    for (int p = 0; p < 2; p++) {
        int k0 = p * 16;
        CP_ASYNC16(sawA[p] + offR0, gA0 + k0);
        CP_ASYNC16(sawA[p] + offR1, gA1 + k0);
        CP_ASYNC16(sawB[p] + offR0, gB0 + k0);
        CP_ASYNC16(sawB[p] + offR1, gB1 + k0);
        CP_COMMIT();
    }

    for (int c = 0; c < NCHUNK; c++) {
        if (c + 2 < NCHUNK) {
            int s = (c + 2) % GSTG;
            int k0 = (c + 2) * 16;
            CP_ASYNC16(sawA[s] + offR0, gA0 + k0);
            CP_ASYNC16(sawA[s] + offR1, gA1 + k0);
            CP_ASYNC16(sawB[s] + offR0, gB0 + k0);
            CP_ASYNC16(sawB[s] + offR1, gB1 + k0);
        }
        CP_COMMIT();
        CP_WAIT(2);
        __syncthreads();

        uint32_t paw = sawA[c % GSTG];
        uint32_t pbw = sawB[c % GSTG];
        #pragma unroll
        for (int ks = 0; ks < 2; ks++) {
            uint32_t kbyte = (uint32_t)(ks * 8 * 4);
            uint32_t af[2][4];
            #pragma unroll
            for (int mt = 0; mt < 2; mt++) {
                uint32_t ad = paw + ((wm + mt * 16 + a_row) * SKW + a_k4) * 4 + kbyte;
                LDSM_X4(af[mt][0], af[mt][1], af[mt][2], af[mt][3], ad);
            }
            uint32_t bf[8][2];
            #pragma unroll
            for (int j = 0; j < 4; j++) {
                uint32_t bd = pbw + ((wn + j * 16 + b_row) * SKW + b_k4) * 4 + kbyte;
                LDSM_X4(bf[2 * j][0], bf[2 * j][1], bf[2 * j + 1][0], bf[2 * j + 1][1], bd);
            }
            #pragma unroll
            for (int mt = 0; mt < 2; mt++)
                #pragma unroll
                for (int nt = 0; nt < 8; nt++)
                    mma_bf16(acc[mt][nt], af[mt], bf[nt]);
        }
        __syncthreads();
    }

    #pragma unroll
    for (int mt = 0; mt < 2; mt++) {
        int r0 = rowBase + wm + mt * 16 + gid;
        #pragma unroll
        for (int nt = 0; nt < 8; nt++) {
            int col = colBase + wn + nt * 8 + tig * 2;
            float2 b2 = *(const float2*)(bias + col);
            float o00 = acc[mt][nt][0] + b2.x, o01 = acc[mt][nt][1] + b2.y;
            float o10 = acc[mt][nt][2] + b2.x, o11 = acc[mt][nt][3] + b2.y;
            if (OUT_BF16) {
                __nv_bfloat16* C16 = (__nv_bfloat16*)Cout;
                *(uint32_t*)(C16 + (size_t)r0 * ldc + col)       = pack_bf16(o00, o01);
                *(uint32_t*)(C16 + (size_t)(r0 + 8) * ldc + col) = pack_bf16(o10, o11);
            } else {
                float* C = (float*)Cout;
                float2 r0v = *(const float2*)(resid + (size_t)r0 * ldc + col);
                float2 r1v = *(const float2*)(resid + (size_t)(r0 + 8) * ldc + col);
                float2 w0 = {o00 + r0v.x, o01 + r0v.y};
                float2 w1 = {o10 + r1v.x, o11 + r1v.y};
                *(float2*)(C + (size_t)r0 * ldc + col)       = w0;
                *(float2*)(C + (size_t)(r0 + 8) * ldc + col) = w1;
            }
        }
    }
}

// ---------------------------------------------------------------------------
// bf16 tensor-core flash attention with ldmatrix fragment loads.
// 128 q-rows/CTA, 64 keys/tile, 256 threads = 8 warps x 16 q-rows.
// __launch_bounds__(256,2) -> regs<=128 -> 2 CTAs/SM.
// ---------------------------------------------------------------------------
#define QSTR 36    // pair stride
#define QKVP (3 * DD / 2)   // 1536 pairs per qkv row

__global__ void __launch_bounds__(256, 2) attn_mma(const float* __restrict__ mask)
{
    extern __shared__ __align__(16) uint32_t sm[];
    uint32_t* Qs  = sm;                     // 128 rows x 36 pairs
    uint32_t* Ks  = Qs + 128 * QSTR;        // 64 rows x 36
    uint32_t* Vt  = Ks + 64 * QSTR;         // 64 dims x 36 (keypairs)
    float*    Msk = (float*)(Vt + 64 * QSTR);  // 64

    int t = threadIdx.x;
    int lane = t & 31, wid = t >> 5;
    int gid = lane >> 2, tig = lane & 3;
    int b = blockIdx.z, h = blockIdx.y, qt = blockIdx.x;
    int qrow0 = b * SS + qt * 128;
    int qr = wid * 16;

    int a_row = lane & 15;
    int a_k4  = (lane >> 4) * 4;
    int b_row = ((lane >> 4) & 1) * 8 + (lane & 7);
    int b_k4  = ((lane >> 3) & 1) * 4;

    uint32_t sawQ = smem_u32(Qs);
    uint32_t sawK = smem_u32(Ks);
    uint32_t sawV = smem_u32(Vt);

    const uint32_t* qkvp = (const uint32_t*)g_qkv16;
    const uint32_t* qbase = qkvp + (size_t)qrow0 * QKVP + h * (HD / 2);

    // stage Q: 128 rows x 32 pairs = 1024 uint4 (4 pairs each)
    #pragma unroll
    for (int i = 0; i < 4; i++) {
        int idx = t + i * 256;
        int r = idx >> 3, q8 = idx & 7;
        *(uint4*)(Qs + r * QSTR + q8 * 4) =
            *(const uint4*)(qbase + (size_t)r * QKVP + q8 * 4);
    }

    float oacc[8][4];
    #pragma unroll
    for (int nd = 0; nd < 8; nd++)
        #pragma unroll
        for (int r = 0; r < 4; r++) oacc[nd][r] = 0.f;
    float mrow[2] = {-1e30f, -1e30f};
    float lrow[2] = {0.f, 0.f};

    for (int kt = 0; kt < SS / 64; kt++) {
        __syncthreads();
        const uint32_t* kbg = qkvp + (size_t)(b * SS + kt * 64) * QKVP
                              + (DD / 2) + h * (HD / 2);
        const uint32_t* vbg = kbg + (DD / 2);
        // K: 64 rows x 32 pairs = 512 uint4
        #pragma unroll
        for (int i = 0; i < 2; i++) {
            int idx = t + i * 256;
            int r = idx >> 3, q8 = idx & 7;
            *(uint4*)(Ks + r * QSTR + q8 * 4) =
                *(const uint4*)(kbg + (size_t)r * QKVP + q8 * 4);
        }
        // V transposed: read uint4 (= 8 dims) of one key, scatter to Vt[dim][key]
        __nv_bfloat16* vt16 = (__nv_bfloat16*)Vt;
        #pragma unroll
        for (int i = 0; i < 2; i++) {
            int idx = t + i * 256;
            int key = idx >> 3, d8 = idx & 7;
            uint4 vv = *(const uint4*)(vbg + (size_t)key * QKVP + d8 * 4);
            const uint32_t* vp = (const uint32_t*)&vv;
            #pragma unroll
            for (int p = 0; p < 4; p++) {
                __nv_bfloat162 pr = *(__nv_bfloat162*)&vp[p];
                int dim = d8 * 8 + p * 2;
                vt16[(size_t)dim * (QSTR * 2) + key]       = pr.x;
                vt16[(size_t)(dim + 1) * (QSTR * 2) + key] = pr.y;
            }
        }
        if (t < 64) Msk[t] = mask[b * SS + kt * 64 + t];
        __syncthreads();

        // ---- S = Q K^T (bf16 m16n8k16, ldmatrix) ----
        float sacc[8][4];
        #pragma unroll
        for (int nt = 0; nt < 8; nt++)
            #pragma unroll
            for (int r = 0; r < 4; r++) sacc[nt][r] = 0.f;

        #pragma unroll
        for (int ks = 0; ks < 4; ks++) {       // 4 k16 steps over 32 pairs
            uint32_t kbyte = (uint32_t)(ks * 8 * 4);
            uint32_t qa[4];
            {
                uint32_t ad = sawQ + ((qr + a_row) * QSTR + a_k4) * 4 + kbyte;
                LDSM_X4(qa[0], qa[1], qa[2], qa[3], ad);
            }
            uint32_t kf[8][2];
            #pragma unroll
            for (int j = 0; j < 4; j++) {
                uint32_t kd = sawK + ((j * 16 + b_row) * QSTR + b_k4) * 4 + kbyte;
                LDSM_X4(kf[2 * j][0], kf[2 * j][1], kf[2 * j + 1][0], kf[2 * j + 1][1], kd);
            }
            #pragma unroll
            for (int nt = 0; nt < 8; nt++)
                mma_bf16(sacc[nt], qa, kf[nt]);
        }

        // ---- online softmax (fp32, C-fragment layout) ----
        {
            float mx0 = mrow[0], mx1 = mrow[1];
            #pragma unroll
            for (int nt = 0; nt < 8; nt++) {
                float mk0 = Msk[nt * 8 + 2 * tig];
                float mk1 = Msk[nt * 8 + 2 * tig + 1];
                float* s = sacc[nt];
                s[0] = s[0] * 0.125f + mk0;
                s[1] = s[1] * 0.125f + mk1;
                s[2] = s[2] * 0.125f + mk0;
                s[3] = s[3] * 0.125f + mk1;
                mx0 = fmaxf(mx0, fmaxf(s[0], s[1]));
                mx1 = fmaxf(mx1, fmaxf(s[2], s[3]));
            }
            mx0 = fmaxf(mx0, __shfl_xor_sync(0xffffffffu, mx0, 1));
            mx0 = fmaxf(mx0, __shfl_xor_sync(0xffffffffu, mx0, 2));
            mx1 = fmaxf(mx1, __shfl_xor_sync(0xffffffffu, mx1, 1));
            mx1 = fmaxf(mx1, __shfl_xor_sync(0xffffffffu, mx1, 2));
            float c0 = __expf(mrow[0] - mx0);
            float c1 = __expf(mrow[1] - mx1);
            mrow[0] = mx0; mrow[1] = mx1;
            float ls0 = 0.f, ls1 = 0.f;
            #pragma unroll
            for (int nt = 0; nt < 8; nt++) {
                float* s = sacc[nt];
                s[0] = __expf(s[0] - mx0);
                s[1] = __expf(s[1] - mx0);
                s[2] = __expf(s[2] - mx1);
                s[3] = __expf(s[3] - mx1);
                ls0 += s[0] + s[1];
                ls1 += s[2] + s[3];
            }
            ls0 += __shfl_xor_sync(0xffffffffu, ls0, 1);
            ls0 += __shfl_xor_sync(0xffffffffu, ls0, 2);
            ls1 += __shfl_xor_sync(0xffffffffu, ls1, 1);
            ls1 += __shfl_xor_sync(0xffffffffu, ls1, 2);
            lrow[0] = lrow[0] * c0 + ls0;
            lrow[1] = lrow[1] * c1 + ls1;
            #pragma unroll
            for (int nd = 0; nd < 8; nd++) {
                float* o = oacc[nd];
                o[0] *= c0; o[1] *= c0; o[2] *= c1; o[3] *= c1;
            }
        }

        // ---- O += P V : pack P from C-fragments, V frags via ldmatrix ----
        #pragma unroll
        for (int j = 0; j < 4; j++) {          // 4 k16 blocks of 16 keys
            uint32_t pa[4];
            float* s0 = sacc[2 * j];
            float* s1 = sacc[2 * j + 1];
            pa[0] = pack_bf16(s0[0], s0[1]);   // row g,   keypair tig
            pa[1] = pack_bf16(s0[2], s0[3]);   // row g+8, keypair tig
            pa[2] = pack_bf16(s1[0], s1[1]);   // row g,   keypair tig+4
            pa[3] = pack_bf16(s1[2], s1[3]);   // row g+8, keypair tig+4
            uint32_t vbf[8][2];
            #pragma unroll
            for (int jj = 0; jj < 4; jj++) {
                uint32_t vd = sawV + ((jj * 16 + b_row) * QSTR + j * 8 + b_k4) * 4;
                LDSM_X4(vbf[2 * jj][0], vbf[2 * jj][1],
                        vbf[2 * jj + 1][0], vbf[2 * jj + 1][1], vd);
            }
            #pragma unroll
            for (int nd = 0; nd < 8; nd++)
                mma_bf16(oacc[nd], pa, vbf[nd]);
        }
    }

    // ---- epilogue: normalize, store ctx as bf16 ----
    {
        float inv0 = 1.f / lrow[0];
        float inv1 = 1.f / lrow[1];
        int r0 = qrow0 + qr + gid;
        #pragma unroll
        for (int nd = 0; nd < 8; nd++) {
            int col = h * HD + nd * 8 + 2 * tig;
            *(uint32_t*)(g_ctx16 + (size_t)r0 * DD + col) =
                pack_bf16(oacc[nd][0] * inv0, oacc[nd][1] * inv0);
            *(uint32_t*)(g_ctx16 + (size_t)(r0 + 8) * DD + col) =
                pack_bf16(oacc[nd][2] * inv1, oacc[nd][3] * inv1);
        }
    }
}

// ---------------------------------------------------------------------------
// Launcher
// ---------------------------------------------------------------------------
extern "C" void kernel_launch(void* const* d_in, const int* in_sizes, int n_in,
                              void* d_out, int out_size)
{
    const float* hidden = (const float*)d_in[0];
    const float* mask   = (const float*)d_in[1];
    const float* gamma  = (const float*)d_in[2];
    const float* beta   = (const float*)d_in[3];
    const float* wq = (const float*)d_in[4];
    const float* bq = (const float*)d_in[5];
    const float* wk = (const float*)d_in[6];
    const float* bk = (const float*)d_in[7];
    const float* wv = (const float*)d_in[8];
    const float* bv = (const float*)d_in[9];
    const float* wo = (const float*)d_in[10];
    const float* bo = (const float*)d_in[11];
    float* out = (float*)d_out;

    void *p_xn, *p_qkv, *p_ctx, *p_w, *p_bqkv;
    cudaGetSymbolAddress(&p_xn,  g_xn16);
    cudaGetSymbolAddress(&p_qkv, g_qkv16);
    cudaGetSymbolAddress(&p_ctx, g_ctx16);
    cudaGetSymbolAddress(&p_w,   g_w16);
    cudaGetSymbolAddress(&p_bqkv, g_bqkv);
    __nv_bfloat16* xn  = (__nv_bfloat16*)p_xn;
    __nv_bfloat16* qkv = (__nv_bfloat16*)p_qkv;
    __nv_bfloat16* ctx = (__nv_bfloat16*)p_ctx;
    __nv_bfloat16* w16 = (__nv_bfloat16*)p_w;
    float* bqkv = (float*)p_bqkv;

    // 0. Prep: bf16 weights, concat qkv bias
    wprep_kernel<<<4 * DD * DD / 4 / 256, 256>>>(wq, wk, wv, wo, w16);
    bprep_kernel<<<3 * DD / 256, 256>>>(bq, bk, bv, bqkv);

    // 1. LayerNorm (bf16 output)
    ln_kernel<<<ROWS, 256>>>(hidden, gamma, beta, xn);

    // 2. Fused QKV projection: [4096,1024] @ [3072,1024]^T -> bf16
    cudaFuncSetAttribute(gemm_mma<true>,
                         cudaFuncAttributeMaxDynamicSharedMemorySize, GSMEM_BYTES);
    cudaFuncSetAttribute(gemm_mma<false>,
                         cudaFuncAttributeMaxDynamicSharedMemorySize, GSMEM_BYTES);
    gemm_mma<true><<<dim3(3 * DD / 128, ROWS / 128), 256, GSMEM_BYTES>>>(
        (const uint32_t*)xn, (const uint32_t*)w16, bqkv, nullptr, qkv, 3 * DD);

    // 3. bf16 tensor-core flash attention
    int smem = (128 * QSTR + 64 * QSTR * 2) * 4 + 64 * 4;
    cudaFuncSetAttribute(attn_mma, cudaFuncAttributeMaxDynamicSharedMemorySize, smem);
    attn_mma<<<dim3(SS / 128, HH, BB), 256, smem>>>(mask);

    // 4. Output projection + bias + residual (fp32 out)
    gemm_mma<false><<<dim3(DD / 128, ROWS / 128), 256, GSMEM_BYTES>>>(
        (const uint32_t*)ctx, (const uint32_t*)(w16 + (size_t)3 * DD * DD),
        bo, hidden, out, DD);
}

// round 16
// speedup vs baseline: 1.3115x; 1.2268x over previous
#include <cuda_runtime.h>
#include <cuda_bf16.h>
#include <cstdint>
#include <math.h>

#define BB 2
#define SS 2048
#define DD 1024
#define HH 16
#define HD 64
#define ROWS (BB*SS)

// Scratch (static device globals — no runtime allocation)
__device__ __nv_bfloat16 g_xn16[ROWS * DD];
__device__ __nv_bfloat16 g_qkv16[ROWS * 3 * DD];
__device__ __nv_bfloat16 g_ctx16[ROWS * DD];
__device__ __nv_bfloat16 g_w16[4 * DD * DD];   // bf16 wq,wk,wv,wo
__device__ float g_bqkv[3 * DD];

// ---------------------------------------------------------------------------
// helpers
// ---------------------------------------------------------------------------
__device__ __forceinline__ uint32_t smem_u32(const void* p) {
    uint32_t a;
    asm("{ .reg .u64 t; cvta.to.shared.u64 t, %1; cvt.u32.u64 %0, t; }"
        : "=r"(a) : "l"(p));
    return a;
}

// pack two fp32 -> bf16x2 (lo = first arg, hi = second), round-to-nearest
__device__ __forceinline__ uint32_t pack_bf16(float lo, float hi) {
    uint32_t d;
    asm("cvt.rn.bf16x2.f32 %0, %1, %2;" : "=r"(d) : "f"(hi), "f"(lo));
    return d;
}

#define CP_ASYNC16(smem_addr, gptr) \
    asm volatile("cp.async.cg.shared.global [%0], [%1], 16;" \
                 :: "r"(smem_addr), "l"(gptr) : "memory")
#define CP_COMMIT() asm volatile("cp.async.commit_group;" ::: "memory")
#define CP_WAIT(N)  asm volatile("cp.async.wait_group %0;" :: "n"(N) : "memory")

#define LDSM_X4(r0, r1, r2, r3, addr) \
    asm volatile("ldmatrix.sync.aligned.m8n8.x4.shared.b16 {%0,%1,%2,%3}, [%4];" \
                 : "=r"(r0), "=r"(r1), "=r"(r2), "=r"(r3) : "r"(addr))

#define LDSM_X4_T(r0, r1, r2, r3, addr) \
    asm volatile("ldmatrix.sync.aligned.m8n8.x4.trans.shared.b16 {%0,%1,%2,%3}, [%4];" \
                 : "=r"(r0), "=r"(r1), "=r"(r2), "=r"(r3) : "r"(addr))

__device__ __forceinline__ void mma_bf16(float* c, const uint32_t* a, const uint32_t* b) {
    asm volatile(
        "mma.sync.aligned.m16n8k16.row.col.f32.bf16.bf16.f32 "
        "{%0,%1,%2,%3}, {%4,%5,%6,%7}, {%8,%9}, {%0,%1,%2,%3};"
        : "+f"(c[0]), "+f"(c[1]), "+f"(c[2]), "+f"(c[3])
        : "r"(a[0]), "r"(a[1]), "r"(a[2]), "r"(a[3]), "r"(b[0]), "r"(b[1]));
}

// ---------------------------------------------------------------------------
// Weight prep: fp32 -> bf16 (rn) for all 4 weight matrices
// ---------------------------------------------------------------------------
__global__ void __launch_bounds__(256) wprep_kernel(
    const float* __restrict__ wq, const float* __restrict__ wk,
    const float* __restrict__ wv, const float* __restrict__ wo,
    __nv_bfloat16* __restrict__ dst)
{
    int i = blockIdx.x * 256 + threadIdx.x;        // float4 index
    const float* srcs[4] = {wq, wk, wv, wo};
    int which = i / (DD * DD / 4);
    int off   = i % (DD * DD / 4);
    float4 v = ((const float4*)srcs[which])[off];
    uint2 o;
    o.x = pack_bf16(v.x, v.y);
    o.y = pack_bf16(v.z, v.w);
    ((uint2*)dst)[i] = o;
}

__global__ void __launch_bounds__(256) bprep_kernel(
    const float* __restrict__ bq, const float* __restrict__ bk,
    const float* __restrict__ bv, float* __restrict__ dst)
{
    int i = blockIdx.x * 256 + threadIdx.x;        // 0..3071
    const float* s = (i < DD) ? bq : ((i < 2 * DD) ? bk : bv);
    dst[i] = s[i & (DD - 1)];
}

// ---------------------------------------------------------------------------
// LayerNorm: one block per row; output bf16
// ---------------------------------------------------------------------------
__global__ void __launch_bounds__(256) ln_kernel(
    const float* __restrict__ x, const float* __restrict__ gamma,
    const float* __restrict__ beta, __nv_bfloat16* __restrict__ out)
{
    int row = blockIdx.x;
    int t = threadIdx.x;
    float4 v = ((const float4*)(x + (size_t)row * DD))[t];
    float s  = v.x + v.y + v.z + v.w;
    float ss = v.x*v.x + v.y*v.y + v.z*v.z + v.w*v.w;

    #pragma unroll
    for (int o = 16; o; o >>= 1) {
        s  += __shfl_xor_sync(0xffffffffu, s,  o);
        ss += __shfl_xor_sync(0xffffffffu, ss, o);
    }
    __shared__ float rs[8], rss[8];
    int w = t >> 5;
    if ((t & 31) == 0) { rs[w] = s; rss[w] = ss; }
    __syncthreads();
    if (t < 32) {
        float a  = (t < 8) ? rs[t]  : 0.f;
        float aa = (t < 8) ? rss[t] : 0.f;
        #pragma unroll
        for (int o = 4; o; o >>= 1) {
            a  += __shfl_xor_sync(0xffffffffu, a,  o);
            aa += __shfl_xor_sync(0xffffffffu, aa, o);
        }
        if (t == 0) { rs[0] = a; rss[0] = aa; }
    }
    __syncthreads();
    float mean = rs[0] * (1.0f / DD);
    float var  = rss[0] * (1.0f / DD) - mean * mean;
    float rstd = rsqrtf(var + 1e-12f);

    float4 g  = ((const float4*)gamma)[t];
    float4 bt = ((const float4*)beta)[t];
    uint2 o;
    o.x = pack_bf16((v.x - mean) * rstd * g.x + bt.x,
                    (v.y - mean) * rstd * g.y + bt.y);
    o.y = pack_bf16((v.z - mean) * rstd * g.z + bt.z,
                    (v.w - mean) * rstd * g.w + bt.w);
    ((uint2*)(out + (size_t)row * DD))[t] = o;
}

// ---------------------------------------------------------------------------
// bf16 mma.sync GEMM-NT, 2-CTA/SM occupancy version (unchanged from R15).
// Block 128x128, 8 warps (4x2) of 32x64. 3-stage cp.async, dynamic smem.
// ---------------------------------------------------------------------------
#define SKW 20
#define GSTG 3
#define GA_STAGE (128 * SKW)
#define GB_STAGE (128 * SKW)
#define GSMEM_BYTES (GSTG * (GA_STAGE + GB_STAGE) * 4)
#define KP (DD / 2)            // 512 pairs per row

template<bool OUT_BF16>
__global__ void __launch_bounds__(256, 2) gemm_mma(
    const uint32_t* __restrict__ A, const uint32_t* __restrict__ W,
    const float* __restrict__ bias, const float* __restrict__ resid,
    void* __restrict__ Cout, int ldc)
{
    extern __shared__ __align__(16) uint32_t gsm[];
    uint32_t* sAb = gsm;
    uint32_t* sBb = gsm + GSTG * GA_STAGE;

    int tid  = threadIdx.x;
    int lane = tid & 31;
    int wid  = tid >> 5;
    int wm = (wid & 3) * 32;       // 4 warp-rows of 32
    int wn = (wid >> 2) * 64;      // 2 warp-cols of 64
    int rowBase = blockIdx.y * 128;
    int colBase = blockIdx.x * 128;
    int gid = lane >> 2;
    int tig = lane & 3;

    int a_row = lane & 15;
    int a_k4  = (lane >> 4) * 4;
    int b_row = ((lane >> 4) & 1) * 8 + (lane & 7);
    int b_k4  = ((lane >> 3) & 1) * 4;

    int lrow = tid >> 2;          // 0..63
    int lc4  = tid & 3;           // 0..3 (16B = 4 pairs each)
    const uint32_t* gA0 = A + (size_t)(rowBase + lrow) * KP + lc4 * 4;
    const uint32_t* gA1 = gA0 + (size_t)64 * KP;
    const uint32_t* gB0 = W + (size_t)(colBase + lrow) * KP + lc4 * 4;
    const uint32_t* gB1 = gB0 + (size_t)64 * KP;

    uint32_t offR0 = (uint32_t)((lrow * SKW + lc4 * 4) * 4);
    uint32_t offR1 = (uint32_t)(((lrow + 64) * SKW + lc4 * 4) * 4);

    uint32_t sawA[GSTG], sawB[GSTG];
    #pragma unroll
    for (int s = 0; s < GSTG; s++) {
        sawA[s] = smem_u32(sAb + s * GA_STAGE);
        sawB[s] = smem_u32(sBb + s * GB_STAGE);
    }

    float acc[2][8][4];
    #pragma unroll
    for (int mt = 0; mt < 2; mt++)
        #pragma unroll
        for (int nt = 0; nt < 8; nt++)
            #pragma unroll
            for (int r = 0; r < 4; r++) acc[mt][nt][r] = 0.f;

    const int NCHUNK = KP / 16;   // 32

    #pragma unroll
    for (int p = 0; p < 2; p++) {
        int k0 = p * 16;
        CP_ASYNC16(sawA[p] + offR0, gA0 + k0);
        CP_ASYNC16(sawA[p] + offR1, gA1 + k0);
        CP_ASYNC16(sawB[p] + offR0, gB0 + k0);
        CP_ASYNC16(sawB[p] + offR1, gB1 + k0);
        CP_COMMIT();
    }

    for (int c = 0; c < NCHUNK; c++) {
        if (c + 2 < NCHUNK) {
            int s = (c + 2) % GSTG;
            int k0 = (c + 2) * 16;
            CP_ASYNC16(sawA[s] + offR0, gA0 + k0);
            CP_ASYNC16(sawA[s] + offR1, gA1 + k0);
            CP_ASYNC16(sawB[s] + offR0, gB0 + k0);
            CP_ASYNC16(sawB[s] + offR1, gB1 + k0);
        }
        CP_COMMIT();
        CP_WAIT(2);
        __syncthreads();

        uint32_t paw = sawA[c % GSTG];
        uint32_t pbw = sawB[c % GSTG];
        #pragma unroll
        for (int ks = 0; ks < 2; ks++) {
            uint32_t kbyte = (uint32_t)(ks * 8 * 4);
            uint32_t af[2][4];
            #pragma unroll
            for (int mt = 0; mt < 2; mt++) {
                uint32_t ad = paw + ((wm + mt * 16 + a_row) * SKW + a_k4) * 4 + kbyte;
                LDSM_X4(af[mt][0], af[mt][1], af[mt][2], af[mt][3], ad);
            }
            uint32_t bf[8][2];
            #pragma unroll
            for (int j = 0; j < 4; j++) {
                uint32_t bd = pbw + ((wn + j * 16 + b_row) * SKW + b_k4) * 4 + kbyte;
                LDSM_X4(bf[2 * j][0], bf[2 * j][1], bf[2 * j + 1][0], bf[2 * j + 1][1], bd);
            }
            #pragma unroll
            for (int mt = 0; mt < 2; mt++)
                #pragma unroll
                for (int nt = 0; nt < 8; nt++)
                    mma_bf16(acc[mt][nt], af[mt], bf[nt]);
        }
        __syncthreads();
    }

    #pragma unroll
    for (int mt = 0; mt < 2; mt++) {
        int r0 = rowBase + wm + mt * 16 + gid;
        #pragma unroll
        for (int nt = 0; nt < 8; nt++) {
            int col = colBase + wn + nt * 8 + tig * 2;
            float2 b2 = *(const float2*)(bias + col);
            float o00 = acc[mt][nt][0] + b2.x, o01 = acc[mt][nt][1] + b2.y;
            float o10 = acc[mt][nt][2] + b2.x, o11 = acc[mt][nt][3] + b2.y;
            if (OUT_BF16) {
                __nv_bfloat16* C16 = (__nv_bfloat16*)Cout;
                *(uint32_t*)(C16 + (size_t)r0 * ldc + col)       = pack_bf16(o00, o01);
                *(uint32_t*)(C16 + (size_t)(r0 + 8) * ldc + col) = pack_bf16(o10, o11);
            } else {
                float* C = (float*)Cout;
                float2 r0v = *(const float2*)(resid + (size_t)r0 * ldc + col);
                float2 r1v = *(const float2*)(resid + (size_t)(r0 + 8) * ldc + col);
                float2 w0 = {o00 + r0v.x, o01 + r0v.y};
                float2 w1 = {o10 + r1v.x, o11 + r1v.y};
                *(float2*)(C + (size_t)r0 * ldc + col)       = w0;
                *(float2*)(C + (size_t)(r0 + 8) * ldc + col) = w1;
            }
        }
    }
}

// ---------------------------------------------------------------------------
// bf16 tensor-core flash attention, v2:
//  - V staged ROW-MAJOR like K (no transpose scatter); PV B-fragments via
//    ldmatrix.x4.trans.
//  - K/V/mask double-buffered with cp.async (prefetch kt+1 during compute kt).
// 128 q-rows/CTA, 64 keys/tile, 256 threads = 8 warps x 16 q-rows, 2 CTAs/SM.
// ---------------------------------------------------------------------------
#define QSTR 36    // pair stride
#define QKVP (3 * DD / 2)   // 1536 pairs per qkv row
#define KV_STAGE (64 * QSTR)
#define ASMEM_WORDS (128 * QSTR + 4 * KV_STAGE + 2 * 64)

__global__ void __launch_bounds__(256, 2) attn_mma(const float* __restrict__ mask)
{
    extern __shared__ __align__(16) uint32_t sm[];
    uint32_t* Qs  = sm;                          // 128 x 36
    uint32_t* Ksb = Qs + 128 * QSTR;             // 2 x (64 x 36)
    uint32_t* Vsb = Ksb + 2 * KV_STAGE;          // 2 x (64 x 36)
    float*    Msk = (float*)(Vsb + 2 * KV_STAGE);// 2 x 64

    int t = threadIdx.x;
    int lane = t & 31, wid = t >> 5;
    int gid = lane >> 2, tig = lane & 3;
    int b = blockIdx.z, h = blockIdx.y, qt = blockIdx.x;
    int qrow0 = b * SS + qt * 128;
    int qr = wid * 16;

    int a_row = lane & 15;
    int a_k4  = (lane >> 4) * 4;
    int b_row = ((lane >> 4) & 1) * 8 + (lane & 7);
    int b_k4  = ((lane >> 3) & 1) * 4;
    // V-trans fragment map: matrices (keys lo/hi) x (dims lo/hi)
    int v_row = ((lane >> 3) & 1) * 8 + (lane & 7);
    int v_c4  = ((lane >> 4) & 1) * 4;

    uint32_t sawQ = smem_u32(Qs);
    uint32_t sawK[2] = { smem_u32(Ksb), smem_u32(Ksb + KV_STAGE) };
    uint32_t sawV[2] = { smem_u32(Vsb), smem_u32(Vsb + KV_STAGE) };
    uint32_t sawM = smem_u32(Msk);

    const uint32_t* qkvp = (const uint32_t*)g_qkv16;
    const uint32_t* qbase = qkvp + (size_t)qrow0 * QKVP + h * (HD / 2);

    // stage Q: 128 rows x 32 pairs = 1024 uint4 (4 pairs each)
    #pragma unroll
    for (int i = 0; i < 4; i++) {
        int idx = t + i * 256;
        int r = idx >> 3, q8 = idx & 7;
        *(uint4*)(Qs + r * QSTR + q8 * 4) =
            *(const uint4*)(qbase + (size_t)r * QKVP + q8 * 4);
    }

    // per-thread staging offsets (2 uint4 each for K and V)
    int sr0 = t >> 3, sq0 = t & 7;                 // idx = t
    int sr1 = (t + 256) >> 3, sq1 = (t + 256) & 7; // idx = t + 256
    uint32_t so0 = (uint32_t)((sr0 * QSTR + sq0 * 4) * 4);
    uint32_t so1 = (uint32_t)((sr1 * QSTR + sq1 * 4) * 4);
    size_t go0 = (size_t)sr0 * QKVP + sq0 * 4;
    size_t go1 = (size_t)sr1 * QKVP + sq1 * 4;

    const float* mbase = mask + b * SS;

    // prefetch tile 0
    {
        const uint32_t* kbg = qkvp + (size_t)(b * SS) * QKVP + (DD / 2) + h * (HD / 2);
        const uint32_t* vbg = kbg + (DD / 2);
        CP_ASYNC16(sawK[0] + so0, kbg + go0);
        CP_ASYNC16(sawK[0] + so1, kbg + go1);
        CP_ASYNC16(sawV[0] + so0, vbg + go0);
        CP_ASYNC16(sawV[0] + so1, vbg + go1);
        if (t < 16) CP_ASYNC16(sawM + t * 16, mbase + t * 4);
        CP_COMMIT();
    }

    float oacc[8][4];
    #pragma unroll
    for (int nd = 0; nd < 8; nd++)
        #pragma unroll
        for (int r = 0; r < 4; r++) oacc[nd][r] = 0.f;
    float mrow[2] = {-1e30f, -1e30f};
    float lrow[2] = {0.f, 0.f};

    for (int kt = 0; kt < SS / 64; kt++) {
        int buf = kt & 1;
        CP_WAIT(0);
        __syncthreads();

        // prefetch next tile into other buffer
        if (kt + 1 < SS / 64) {
            const uint32_t* kbg = qkvp + (size_t)(b * SS + (kt + 1) * 64) * QKVP
                                  + (DD / 2) + h * (HD / 2);
            const uint32_t* vbg = kbg + (DD / 2);
            int nb = buf ^ 1;
            CP_ASYNC16(sawK[nb] + so0, kbg + go0);
            CP_ASYNC16(sawK[nb] + so1, kbg + go1);
            CP_ASYNC16(sawV[nb] + so0, vbg + go0);
            CP_ASYNC16(sawV[nb] + so1, vbg + go1);
            if (t < 16) CP_ASYNC16(sawM + nb * 256 + t * 16,
                                   mbase + (kt + 1) * 64 + t * 4);
            CP_COMMIT();
        }

        const float* mskb = Msk + buf * 64;

        // ---- S = Q K^T (bf16 m16n8k16, ldmatrix) ----
        float sacc[8][4];
        #pragma unroll
        for (int nt = 0; nt < 8; nt++)
            #pragma unroll
            for (int r = 0; r < 4; r++) sacc[nt][r] = 0.f;

        #pragma unroll
        for (int ks = 0; ks < 4; ks++) {       // 4 k16 steps over 32 pairs
            uint32_t kbyte = (uint32_t)(ks * 8 * 4);
            uint32_t qa[4];
            {
                uint32_t ad = sawQ + ((qr + a_row) * QSTR + a_k4) * 4 + kbyte;
                LDSM_X4(qa[0], qa[1], qa[2], qa[3], ad);
            }
            uint32_t kf[8][2];
            #pragma unroll
            for (int j = 0; j < 4; j++) {
                uint32_t kd = sawK[buf] + ((j * 16 + b_row) * QSTR + b_k4) * 4 + kbyte;
                LDSM_X4(kf[2 * j][0], kf[2 * j][1], kf[2 * j + 1][0], kf[2 * j + 1][1], kd);
            }
            #pragma unroll
            for (int nt = 0; nt < 8; nt++)
                mma_bf16(sacc[nt], qa, kf[nt]);
        }

        // ---- online softmax (fp32, C-fragment layout) ----
        {
            float mx0 = mrow[0], mx1 = mrow[1];
            #pragma unroll
            for (int nt = 0; nt < 8; nt++) {
                float mk0 = mskb[nt * 8 + 2 * tig];
                float mk1 = mskb[nt * 8 + 2 * tig + 1];
                float* s = sacc[nt];
                s[0] = s[0] * 0.125f + mk0;
                s[1] = s[1] * 0.125f + mk1;
                s[2] = s[2] * 0.125f + mk0;
                s[3] = s[3] * 0.125f + mk1;
                mx0 = fmaxf(mx0, fmaxf(s[0], s[1]));
                mx1 = fmaxf(mx1, fmaxf(s[2], s[3]));
            }
            mx0 = fmaxf(mx0, __shfl_xor_sync(0xffffffffu, mx0, 1));
            mx0 = fmaxf(mx0, __shfl_xor_sync(0xffffffffu, mx0, 2));
            mx1 = fmaxf(mx1, __shfl_xor_sync(0xffffffffu, mx1, 1));
            mx1 = fmaxf(mx1, __shfl_xor_sync(0xffffffffu, mx1, 2));
            float c0 = __expf(mrow[0] - mx0);
            float c1 = __expf(mrow[1] - mx1);
            mrow[0] = mx0; mrow[1] = mx1;
            float ls0 = 0.f, ls1 = 0.f;
            #pragma unroll
            for (int nt = 0; nt < 8; nt++) {
                float* s = sacc[nt];
                s[0] = __expf(s[0] - mx0);
                s[1] = __expf(s[1] - mx0);
                s[2] = __expf(s[2] - mx1);
                s[3] = __expf(s[3] - mx1);
                ls0 += s[0] + s[1];
                ls1 += s[2] + s[3];
            }
            ls0 += __shfl_xor_sync(0xffffffffu, ls0, 1);
            ls0 += __shfl_xor_sync(0xffffffffu, ls0, 2);
            ls1 += __shfl_xor_sync(0xffffffffu, ls1, 1);
            ls1 += __shfl_xor_sync(0xffffffffu, ls1, 2);
            lrow[0] = lrow[0] * c0 + ls0;
            lrow[1] = lrow[1] * c1 + ls1;
            #pragma unroll
            for (int nd = 0; nd < 8; nd++) {
                float* o = oacc[nd];
                o[0] *= c0; o[1] *= c0; o[2] *= c1; o[3] *= c1;
            }
        }

        // ---- O += P V : P from C-fragments; V frags via ldmatrix.trans ----
        #pragma unroll
        for (int j = 0; j < 4; j++) {          // 4 k16 blocks of 16 keys
            uint32_t pa[4];
            float* s0 = sacc[2 * j];
            float* s1 = sacc[2 * j + 1];
            pa[0] = pack_bf16(s0[0], s0[1]);
            pa[1] = pack_bf16(s0[2], s0[3]);
            pa[2] = pack_bf16(s1[0], s1[1]);
            pa[3] = pack_bf16(s1[2], s1[3]);
            uint32_t vbf[8][2];
            #pragma unroll
            for (int jj = 0; jj < 4; jj++) {
                uint32_t vd = sawV[buf] + ((j * 16 + v_row) * QSTR + jj * 8 + v_c4) * 4;
                LDSM_X4_T(vbf[2 * jj][0], vbf[2 * jj][1],
                          vbf[2 * jj + 1][0], vbf[2 * jj + 1][1], vd);
            }
            #pragma unroll
            for (int nd = 0; nd < 8; nd++)
                mma_bf16(oacc[nd], pa, vbf[nd]);
        }
    }

    // ---- epilogue: normalize, store ctx as bf16 ----
    {
        float inv0 = 1.f / lrow[0];
        float inv1 = 1.f / lrow[1];
        int r0 = qrow0 + qr + gid;
        #pragma unroll
        for (int nd = 0; nd < 8; nd++) {
            int col = h * HD + nd * 8 + 2 * tig;
            *(uint32_t*)(g_ctx16 + (size_t)r0 * DD + col) =
                pack_bf16(oacc[nd][0] * inv0, oacc[nd][1] * inv0);
            *(uint32_t*)(g_ctx16 + (size_t)(r0 + 8) * DD + col) =
                pack_bf16(oacc[nd][2] * inv1, oacc[nd][3] * inv1);
        }
    }
}

// ---------------------------------------------------------------------------
// Launcher
// ---------------------------------------------------------------------------
extern "C" void kernel_launch(void* const* d_in, const int* in_sizes, int n_in,
                              void* d_out, int out_size)
{
    const float* hidden = (const float*)d_in[0];
    const float* mask   = (const float*)d_in[1];
    const float* gamma  = (const float*)d_in[2];
    const float* beta   = (const float*)d_in[3];
    const float* wq = (const float*)d_in[4];
    const float* bq = (const float*)d_in[5];
    const float* wk = (const float*)d_in[6];
    const float* bk = (const float*)d_in[7];
    const float* wv = (const float*)d_in[8];
    const float* bv = (const float*)d_in[9];
    const float* wo = (const float*)d_in[10];
    const float* bo = (const float*)d_in[11];
    float* out = (float*)d_out;

    void *p_xn, *p_qkv, *p_ctx, *p_w, *p_bqkv;
    cudaGetSymbolAddress(&p_xn,  g_xn16);
    cudaGetSymbolAddress(&p_qkv, g_qkv16);
    cudaGetSymbolAddress(&p_ctx, g_ctx16);
    cudaGetSymbolAddress(&p_w,   g_w16);
    cudaGetSymbolAddress(&p_bqkv, g_bqkv);
    __nv_bfloat16* xn  = (__nv_bfloat16*)p_xn;
    __nv_bfloat16* qkv = (__nv_bfloat16*)p_qkv;
    __nv_bfloat16* ctx = (__nv_bfloat16*)p_ctx;
    __nv_bfloat16* w16 = (__nv_bfloat16*)p_w;
    float* bqkv = (float*)p_bqkv;

    // 0. Prep: bf16 weights, concat qkv bias
    wprep_kernel<<<4 * DD * DD / 4 / 256, 256>>>(wq, wk, wv, wo, w16);
    bprep_kernel<<<3 * DD / 256, 256>>>(bq, bk, bv, bqkv);

    // 1. LayerNorm (bf16 output)
    ln_kernel<<<ROWS, 256>>>(hidden, gamma, beta, xn);

    // 2. Fused QKV projection: [4096,1024] @ [3072,1024]^T -> bf16
    cudaFuncSetAttribute(gemm_mma<true>,
                         cudaFuncAttributeMaxDynamicSharedMemorySize, GSMEM_BYTES);
    cudaFuncSetAttribute(gemm_mma<false>,
                         cudaFuncAttributeMaxDynamicSharedMemorySize, GSMEM_BYTES);
    gemm_mma<true><<<dim3(3 * DD / 128, ROWS / 128), 256, GSMEM_BYTES>>>(
        (const uint32_t*)xn, (const uint32_t*)w16, bqkv, nullptr, qkv, 3 * DD);

    // 3. bf16 tensor-core flash attention (double-buffered, trans-V)
    int smem = ASMEM_WORDS * 4;
    cudaFuncSetAttribute(attn_mma, cudaFuncAttributeMaxDynamicSharedMemorySize, smem);
    attn_mma<<<dim3(SS / 128, HH, BB), 256, smem>>>(mask);

    // 4. Output projection + bias + residual (fp32 out)
    gemm_mma<false><<<dim3(DD / 128, ROWS / 128), 256, GSMEM_BYTES>>>(
        (const uint32_t*)ctx, (const uint32_t*)(w16 + (size_t)3 * DD * DD),
        bo, hidden, out, DD);
}

// round 17
// speedup vs baseline: 1.3607x; 1.0375x over previous
#include <cuda_runtime.h>
#include <cuda_bf16.h>
#include <cstdint>
#include <math.h>

#define BB 2
#define SS 2048
#define DD 1024
#define HH 16
#define HD 64
#define ROWS (BB*SS)

// Scratch (static device globals — no runtime allocation)
__device__ __nv_bfloat16 g_xn16[ROWS * DD];
__device__ __nv_bfloat16 g_qkv16[ROWS * 3 * DD];
__device__ __nv_bfloat16 g_ctx16[ROWS * DD];
__device__ __nv_bfloat16 g_w16[4 * DD * DD];   // bf16 wq,wk,wv,wo
__device__ float g_bqkv[3 * DD];

// ---------------------------------------------------------------------------
// helpers
// ---------------------------------------------------------------------------
__device__ __forceinline__ uint32_t smem_u32(const void* p) {
    uint32_t a;
    asm("{ .reg .u64 t; cvta.to.shared.u64 t, %1; cvt.u32.u64 %0, t; }"
        : "=r"(a) : "l"(p));
    return a;
}

// pack two fp32 -> bf16x2 (lo = first arg, hi = second), round-to-nearest
__device__ __forceinline__ uint32_t pack_bf16(float lo, float hi) {
    uint32_t d;
    asm("cvt.rn.bf16x2.f32 %0, %1, %2;" : "=r"(d) : "f"(hi), "f"(lo));
    return d;
}

#define CP_ASYNC16(smem_addr, gptr) \
    asm volatile("cp.async.cg.shared.global [%0], [%1], 16;" \
                 :: "r"(smem_addr), "l"(gptr) : "memory")
#define CP_COMMIT() asm volatile("cp.async.commit_group;" ::: "memory")
#define CP_WAIT(N)  asm volatile("cp.async.wait_group %0;" :: "n"(N) : "memory")

#define LDSM_X4(r0, r1, r2, r3, addr) \
    asm volatile("ldmatrix.sync.aligned.m8n8.x4.shared.b16 {%0,%1,%2,%3}, [%4];" \
                 : "=r"(r0), "=r"(r1), "=r"(r2), "=r"(r3) : "r"(addr))

#define LDSM_X4_T(r0, r1, r2, r3, addr) \
    asm volatile("ldmatrix.sync.aligned.m8n8.x4.trans.shared.b16 {%0,%1,%2,%3}, [%4];" \
                 : "=r"(r0), "=r"(r1), "=r"(r2), "=r"(r3) : "r"(addr))

__device__ __forceinline__ void mma_bf16(float* c, const uint32_t* a, const uint32_t* b) {
    asm volatile(
        "mma.sync.aligned.m16n8k16.row.col.f32.bf16.bf16.f32 "
        "{%0,%1,%2,%3}, {%4,%5,%6,%7}, {%8,%9}, {%0,%1,%2,%3};"
        : "+f"(c[0]), "+f"(c[1]), "+f"(c[2]), "+f"(c[3])
        : "r"(a[0]), "r"(a[1]), "r"(a[2]), "r"(a[3]), "r"(b[0]), "r"(b[1]));
}

// ---------------------------------------------------------------------------
// Weight prep: fp32 -> bf16 (rn) for all 4 weight matrices
// ---------------------------------------------------------------------------
__global__ void __launch_bounds__(256) wprep_kernel(
    const float* __restrict__ wq, const float* __restrict__ wk,
    const float* __restrict__ wv, const float* __restrict__ wo,
    __nv_bfloat16* __restrict__ dst)
{
    int i = blockIdx.x * 256 + threadIdx.x;        // float4 index
    const float* srcs[4] = {wq, wk, wv, wo};
    int which = i / (DD * DD / 4);
    int off   = i % (DD * DD / 4);
    float4 v = ((const float4*)srcs[which])[off];
    uint2 o;
    o.x = pack_bf16(v.x, v.y);
    o.y = pack_bf16(v.z, v.w);
    ((uint2*)dst)[i] = o;
}

__global__ void __launch_bounds__(256) bprep_kernel(
    const float* __restrict__ bq, const float* __restrict__ bk,
    const float* __restrict__ bv, float* __restrict__ dst)
{
    int i = blockIdx.x * 256 + threadIdx.x;        // 0..3071
    const float* s = (i < DD) ? bq : ((i < 2 * DD) ? bk : bv);
    dst[i] = s[i & (DD - 1)];
}

// ---------------------------------------------------------------------------
// LayerNorm: one block per row; output bf16
// ---------------------------------------------------------------------------
__global__ void __launch_bounds__(256) ln_kernel(
    const float* __restrict__ x, const float* __restrict__ gamma,
    const float* __restrict__ beta, __nv_bfloat16* __restrict__ out)
{
    int row = blockIdx.x;
    int t = threadIdx.x;
    float4 v = ((const float4*)(x + (size_t)row * DD))[t];
    float s  = v.x + v.y + v.z + v.w;
    float ss = v.x*v.x + v.y*v.y + v.z*v.z + v.w*v.w;

    #pragma unroll
    for (int o = 16; o; o >>= 1) {
        s  += __shfl_xor_sync(0xffffffffu, s,  o);
        ss += __shfl_xor_sync(0xffffffffu, ss, o);
    }
    __shared__ float rs[8], rss[8];
    int w = t >> 5;
    if ((t & 31) == 0) { rs[w] = s; rss[w] = ss; }
    __syncthreads();
    if (t < 32) {
        float a  = (t < 8) ? rs[t]  : 0.f;
        float aa = (t < 8) ? rss[t] : 0.f;
        #pragma unroll
        for (int o = 4; o; o >>= 1) {
            a  += __shfl_xor_sync(0xffffffffu, a,  o);
            aa += __shfl_xor_sync(0xffffffffu, aa, o);
        }
        if (t == 0) { rs[0] = a; rss[0] = aa; }
    }
    __syncthreads();
    float mean = rs[0] * (1.0f / DD);
    float var  = rss[0] * (1.0f / DD) - mean * mean;
    float rstd = rsqrtf(var + 1e-12f);

    float4 g  = ((const float4*)gamma)[t];
    float4 bt = ((const float4*)beta)[t];
    uint2 o;
    o.x = pack_bf16((v.x - mean) * rstd * g.x + bt.x,
                    (v.y - mean) * rstd * g.y + bt.y);
    o.y = pack_bf16((v.z - mean) * rstd * g.z + bt.z,
                    (v.w - mean) * rstd * g.w + bt.w);
    ((uint2*)(out + (size_t)row * DD))[t] = o;
}

// ---------------------------------------------------------------------------
// bf16 mma.sync GEMM-NT, BK=64 elems (32 pairs), 2-stage double buffer.
// Block 128x128, 8 warps (4x2) of 32x64. 2 CTAs/SM. 16 chunks -> 32 syncs.
// ---------------------------------------------------------------------------
#define SKW 36                 // pair stride per row (32 + 4 pad)
#define GSTG 2
#define G_STAGE (128 * SKW)    // one tile (A or B)
#define GSMEM_BYTES (GSTG * 2 * G_STAGE * 4)
#define KP (DD / 2)            // 512 pairs per row

template<bool OUT_BF16>
__global__ void __launch_bounds__(256, 2) gemm_mma(
    const uint32_t* __restrict__ A, const uint32_t* __restrict__ W,
    const float* __restrict__ bias, const float* __restrict__ resid,
    void* __restrict__ Cout, int ldc)
{
    extern __shared__ __align__(16) uint32_t gsm[];
    uint32_t* sAb = gsm;                    // GSTG stages of 128*SKW
    uint32_t* sBb = gsm + GSTG * G_STAGE;   // GSTG stages of 128*SKW

    int tid  = threadIdx.x;
    int lane = tid & 31;
    int wid  = tid >> 5;
    int wm = (wid & 3) * 32;       // 4 warp-rows of 32
    int wn = (wid >> 2) * 64;      // 2 warp-cols of 64
    int rowBase = blockIdx.y * 128;
    int colBase = blockIdx.x * 128;
    int gid = lane >> 2;
    int tig = lane & 3;

    int a_row = lane & 15;
    int a_k4  = (lane >> 4) * 4;
    int b_row = ((lane >> 4) & 1) * 8 + (lane & 7);
    int b_k4  = ((lane >> 3) & 1) * 4;

    // staging: tile = 128 rows x 8 uint4; idx = t + i*256 -> row = r0+32i, q8
    int r0 = tid >> 3;            // 0..31
    int q8 = tid & 7;             // 0..7
    const uint32_t* gA = A + (size_t)(rowBase + r0) * KP + q8 * 4;
    const uint32_t* gB = W + (size_t)(colBase + r0) * KP + q8 * 4;
    uint32_t soff = (uint32_t)((r0 * SKW + q8 * 4) * 4);

    uint32_t sawA[GSTG], sawB[GSTG];
    #pragma unroll
    for (int s = 0; s < GSTG; s++) {
        sawA[s] = smem_u32(sAb + s * G_STAGE);
        sawB[s] = smem_u32(sBb + s * G_STAGE);
    }

    float acc[2][8][4];
    #pragma unroll
    for (int mt = 0; mt < 2; mt++)
        #pragma unroll
        for (int nt = 0; nt < 8; nt++)
            #pragma unroll
            for (int r = 0; r < 4; r++) acc[mt][nt][r] = 0.f;

    const int NCHUNK = KP / 32;   // 16

    // prefetch chunk 0 into stage 0
    {
        #pragma unroll
        for (int i = 0; i < 4; i++) {
            size_t gofs = (size_t)(32 * i) * KP;
            uint32_t sofs = (uint32_t)(32 * i * SKW * 4);
            CP_ASYNC16(sawA[0] + soff + sofs, gA + gofs);
            CP_ASYNC16(sawB[0] + soff + sofs, gB + gofs);
        }
        CP_COMMIT();
    }

    for (int c = 0; c < NCHUNK; c++) {
        int buf = c & 1;
        if (c + 1 < NCHUNK) {
            int nb = buf ^ 1;
            int k0 = (c + 1) * 32;
            #pragma unroll
            for (int i = 0; i < 4; i++) {
                size_t gofs = (size_t)(32 * i) * KP + k0;
                uint32_t sofs = (uint32_t)(32 * i * SKW * 4);
                CP_ASYNC16(sawA[nb] + soff + sofs, gA + gofs);
                CP_ASYNC16(sawB[nb] + soff + sofs, gB + gofs);
            }
        }
        CP_COMMIT();              // (possibly empty) keeps group count aligned
        CP_WAIT(1);
        __syncthreads();

        uint32_t paw = sawA[buf];
        uint32_t pbw = sawB[buf];
        #pragma unroll
        for (int ks = 0; ks < 4; ks++) {      // 4 k16 steps over 32 pairs
            uint32_t kbyte = (uint32_t)(ks * 8 * 4);
            uint32_t af[2][4];
            #pragma unroll
            for (int mt = 0; mt < 2; mt++) {
                uint32_t ad = paw + ((wm + mt * 16 + a_row) * SKW + a_k4) * 4 + kbyte;
                LDSM_X4(af[mt][0], af[mt][1], af[mt][2], af[mt][3], ad);
            }
            uint32_t bf[8][2];
            #pragma unroll
            for (int j = 0; j < 4; j++) {
                uint32_t bd = pbw + ((wn + j * 16 + b_row) * SKW + b_k4) * 4 + kbyte;
                LDSM_X4(bf[2 * j][0], bf[2 * j][1], bf[2 * j + 1][0], bf[2 * j + 1][1], bd);
            }
            #pragma unroll
            for (int mt = 0; mt < 2; mt++)
                #pragma unroll
                for (int nt = 0; nt < 8; nt++)
                    mma_bf16(acc[mt][nt], af[mt], bf[nt]);
        }
        __syncthreads();
    }

    #pragma unroll
    for (int mt = 0; mt < 2; mt++) {
        int rr = rowBase + wm + mt * 16 + gid;
        #pragma unroll
        for (int nt = 0; nt < 8; nt++) {
            int col = colBase + wn + nt * 8 + tig * 2;
            float2 b2 = *(const float2*)(bias + col);
            float o00 = acc[mt][nt][0] + b2.x, o01 = acc[mt][nt][1] + b2.y;
            float o10 = acc[mt][nt][2] + b2.x, o11 = acc[mt][nt][3] + b2.y;
            if (OUT_BF16) {
                __nv_bfloat16* C16 = (__nv_bfloat16*)Cout;
                *(uint32_t*)(C16 + (size_t)rr * ldc + col)       = pack_bf16(o00, o01);
                *(uint32_t*)(C16 + (size_t)(rr + 8) * ldc + col) = pack_bf16(o10, o11);
            } else {
                float* C = (float*)Cout;
                float2 r0v = *(const float2*)(resid + (size_t)rr * ldc + col);
                float2 r1v = *(const float2*)(resid + (size_t)(rr + 8) * ldc + col);
                float2 w0 = {o00 + r0v.x, o01 + r0v.y};
                float2 w1 = {o10 + r1v.x, o11 + r1v.y};
                *(float2*)(C + (size_t)rr * ldc + col)       = w0;
                *(float2*)(C + (size_t)(rr + 8) * ldc + col) = w1;
            }
        }
    }
}

// ---------------------------------------------------------------------------
// bf16 tensor-core flash attention (unchanged from R16):
//  - V row-major, PV B-fragments via ldmatrix.x4.trans
//  - K/V/mask double-buffered cp.async
// 128 q-rows/CTA, 64 keys/tile, 256 threads = 8 warps x 16 q-rows, 2 CTAs/SM.
// ---------------------------------------------------------------------------
#define QSTR 36    // pair stride
#define QKVP (3 * DD / 2)   // 1536 pairs per qkv row
#define KV_STAGE (64 * QSTR)
#define ASMEM_WORDS (128 * QSTR + 4 * KV_STAGE + 2 * 64)

__global__ void __launch_bounds__(256, 2) attn_mma(const float* __restrict__ mask)
{
    extern __shared__ __align__(16) uint32_t sm[];
    uint32_t* Qs  = sm;                          // 128 x 36
    uint32_t* Ksb = Qs + 128 * QSTR;             // 2 x (64 x 36)
    uint32_t* Vsb = Ksb + 2 * KV_STAGE;          // 2 x (64 x 36)
    float*    Msk = (float*)(Vsb + 2 * KV_STAGE);// 2 x 64

    int t = threadIdx.x;
    int lane = t & 31, wid = t >> 5;
    int gid = lane >> 2, tig = lane & 3;
    int b = blockIdx.z, h = blockIdx.y, qt = blockIdx.x;
    int qrow0 = b * SS + qt * 128;
    int qr = wid * 16;

    int a_row = lane & 15;
    int a_k4  = (lane >> 4) * 4;
    int b_row = ((lane >> 4) & 1) * 8 + (lane & 7);
    int b_k4  = ((lane >> 3) & 1) * 4;
    int v_row = ((lane >> 3) & 1) * 8 + (lane & 7);
    int v_c4  = ((lane >> 4) & 1) * 4;

    uint32_t sawQ = smem_u32(Qs);
    uint32_t sawK[2] = { smem_u32(Ksb), smem_u32(Ksb + KV_STAGE) };
    uint32_t sawV[2] = { smem_u32(Vsb), smem_u32(Vsb + KV_STAGE) };
    uint32_t sawM = smem_u32(Msk);

    const uint32_t* qkvp = (const uint32_t*)g_qkv16;
    const uint32_t* qbase = qkvp + (size_t)qrow0 * QKVP + h * (HD / 2);

    // stage Q: 128 rows x 32 pairs = 1024 uint4 (4 pairs each)
    #pragma unroll
    for (int i = 0; i < 4; i++) {
        int idx = t + i * 256;
        int r = idx >> 3, q8 = idx & 7;
        *(uint4*)(Qs + r * QSTR + q8 * 4) =
            *(const uint4*)(qbase + (size_t)r * QKVP + q8 * 4);
    }

    // per-thread staging offsets (2 uint4 each for K and V)
    int sr0 = t >> 3, sq0 = t & 7;
    int sr1 = (t + 256) >> 3, sq1 = (t + 256) & 7;
    uint32_t so0 = (uint32_t)((sr0 * QSTR + sq0 * 4) * 4);
    uint32_t so1 = (uint32_t)((sr1 * QSTR + sq1 * 4) * 4);
    size_t go0 = (size_t)sr0 * QKVP + sq0 * 4;
    size_t go1 = (size_t)sr1 * QKVP + sq1 * 4;

    const float* mbase = mask + b * SS;

    // prefetch tile 0
    {
        const uint32_t* kbg = qkvp + (size_t)(b * SS) * QKVP + (DD / 2) + h * (HD / 2);
        const uint32_t* vbg = kbg + (DD / 2);
        CP_ASYNC16(sawK[0] + so0, kbg + go0);
        CP_ASYNC16(sawK[0] + so1, kbg + go1);
        CP_ASYNC16(sawV[0] + so0, vbg + go0);
        CP_ASYNC16(sawV[0] + so1, vbg + go1);
        if (t < 16) CP_ASYNC16(sawM + t * 16, mbase + t * 4);
        CP_COMMIT();
    }

    float oacc[8][4];
    #pragma unroll
    for (int nd = 0; nd < 8; nd++)
        #pragma unroll
        for (int r = 0; r < 4; r++) oacc[nd][r] = 0.f;
    float mrow[2] = {-1e30f, -1e30f};
    float lrow[2] = {0.f, 0.f};

    for (int kt = 0; kt < SS / 64; kt++) {
        int buf = kt & 1;
        CP_WAIT(0);
        __syncthreads();

        // prefetch next tile into other buffer
        if (kt + 1 < SS / 64) {
            const uint32_t* kbg = qkvp + (size_t)(b * SS + (kt + 1) * 64) * QKVP
                                  + (DD / 2) + h * (HD / 2);
            const uint32_t* vbg = kbg + (DD / 2);
            int nb = buf ^ 1;
            CP_ASYNC16(sawK[nb] + so0, kbg + go0);
            CP_ASYNC16(sawK[nb] + so1, kbg + go1);
            CP_ASYNC16(sawV[nb] + so0, vbg + go0);
            CP_ASYNC16(sawV[nb] + so1, vbg + go1);
            if (t < 16) CP_ASYNC16(sawM + nb * 256 + t * 16,
                                   mbase + (kt + 1) * 64 + t * 4);
            CP_COMMIT();
        }

        const float* mskb = Msk + buf * 64;

        // ---- S = Q K^T (bf16 m16n8k16, ldmatrix) ----
        float sacc[8][4];
        #pragma unroll
        for (int nt = 0; nt < 8; nt++)
            #pragma unroll
            for (int r = 0; r < 4; r++) sacc[nt][r] = 0.f;

        #pragma unroll
        for (int ks = 0; ks < 4; ks++) {       // 4 k16 steps over 32 pairs
            uint32_t kbyte = (uint32_t)(ks * 8 * 4);
            uint32_t qa[4];
            {
                uint32_t ad = sawQ + ((qr + a_row) * QSTR + a_k4) * 4 + kbyte;
                LDSM_X4(qa[0], qa[1], qa[2], qa[3], ad);
            }
            uint32_t kf[8][2];
            #pragma unroll
            for (int j = 0; j < 4; j++) {
                uint32_t kd = sawK[buf] + ((j * 16 + b_row) * QSTR + b_k4) * 4 + kbyte;
                LDSM_X4(kf[2 * j][0], kf[2 * j][1], kf[2 * j + 1][0], kf[2 * j + 1][1], kd);
            }
            #pragma unroll
            for (int nt = 0; nt < 8; nt++)
                mma_bf16(sacc[nt], qa, kf[nt]);
        }

        // ---- online softmax (fp32, C-fragment layout) ----
        {
            float mx0 = mrow[0], mx1 = mrow[1];
            #pragma unroll
            for (int nt = 0; nt < 8; nt++) {
                float mk0 = mskb[nt * 8 + 2 * tig];
                float mk1 = mskb[nt * 8 + 2 * tig + 1];
                float* s = sacc[nt];
                s[0] = s[0] * 0.125f + mk0;
                s[1] = s[1] * 0.125f + mk1;
                s[2] = s[2] * 0.125f + mk0;
                s[3] = s[3] * 0.125f + mk1;
                mx0 = fmaxf(mx0, fmaxf(s[0], s[1]));
                mx1 = fmaxf(mx1, fmaxf(s[2], s[3]));
            }
            mx0 = fmaxf(mx0, __shfl_xor_sync(0xffffffffu, mx0, 1));
            mx0 = fmaxf(mx0, __shfl_xor_sync(0xffffffffu, mx0, 2));
            mx1 = fmaxf(mx1, __shfl_xor_sync(0xffffffffu, mx1, 1));
            mx1 = fmaxf(mx1, __shfl_xor_sync(0xffffffffu, mx1, 2));
            float c0 = __expf(mrow[0] - mx0);
            float c1 = __expf(mrow[1] - mx1);
            mrow[0] = mx0; mrow[1] = mx1;
            float ls0 = 0.f, ls1 = 0.f;
            #pragma unroll
            for (int nt = 0; nt < 8; nt++) {
                float* s = sacc[nt];
                s[0] = __expf(s[0] - mx0);
                s[1] = __expf(s[1] - mx0);
                s[2] = __expf(s[2] - mx1);
                s[3] = __expf(s[3] - mx1);
                ls0 += s[0] + s[1];
                ls1 += s[2] + s[3];
            }
            ls0 += __shfl_xor_sync(0xffffffffu, ls0, 1);
            ls0 += __shfl_xor_sync(0xffffffffu, ls0, 2);
            ls1 += __shfl_xor_sync(0xffffffffu, ls1, 1);
            ls1 += __shfl_xor_sync(0xffffffffu, ls1, 2);
            lrow[0] = lrow[0] * c0 + ls0;
            lrow[1] = lrow[1] * c1 + ls1;
            #pragma unroll
            for (int nd = 0; nd < 8; nd++) {
                float* o = oacc[nd];
                o[0] *= c0; o[1] *= c0; o[2] *= c1; o[3] *= c1;
            }
        }

        // ---- O += P V : P from C-fragments; V frags via ldmatrix.trans ----
        #pragma unroll
        for (int j = 0; j < 4; j++) {          // 4 k16 blocks of 16 keys
            uint32_t pa[4];
            float* s0 = sacc[2 * j];
            float* s1 = sacc[2 * j + 1];
            pa[0] = pack_bf16(s0[0], s0[1]);
            pa[1] = pack_bf16(s0[2], s0[3]);
            pa[2] = pack_bf16(s1[0], s1[1]);
            pa[3] = pack_bf16(s1[2], s1[3]);
            uint32_t vbf[8][2];
            #pragma unroll
            for (int jj = 0; jj < 4; jj++) {
                uint32_t vd = sawV[buf] + ((j * 16 + v_row) * QSTR + jj * 8 + v_c4) * 4;
                LDSM_X4_T(vbf[2 * jj][0], vbf[2 * jj][1],
                          vbf[2 * jj + 1][0], vbf[2 * jj + 1][1], vd);
            }
            #pragma unroll
            for (int nd = 0; nd < 8; nd++)
                mma_bf16(oacc[nd], pa, vbf[nd]);
        }
    }

    // ---- epilogue: normalize, store ctx as bf16 ----
    {
        float inv0 = 1.f / lrow[0];
        float inv1 = 1.f / lrow[1];
        int r0 = qrow0 + qr + gid;
        #pragma unroll
        for (int nd = 0; nd < 8; nd++) {
            int col = h * HD + nd * 8 + 2 * tig;
            *(uint32_t*)(g_ctx16 + (size_t)r0 * DD + col) =
                pack_bf16(oacc[nd][0] * inv0, oacc[nd][1] * inv0);
            *(uint32_t*)(g_ctx16 + (size_t)(r0 + 8) * DD + col) =
                pack_bf16(oacc[nd][2] * inv1, oacc[nd][3] * inv1);
        }
    }
}

// ---------------------------------------------------------------------------
// Launcher
// ---------------------------------------------------------------------------
extern "C" void kernel_launch(void* const* d_in, const int* in_sizes, int n_in,
                              void* d_out, int out_size)
{
    const float* hidden = (const float*)d_in[0];
    const float* mask   = (const float*)d_in[1];
    const float* gamma  = (const float*)d_in[2];
    const float* beta   = (const float*)d_in[3];
    const float* wq = (const float*)d_in[4];
    const float* bq = (const float*)d_in[5];
    const float* wk = (const float*)d_in[6];
    const float* bk = (const float*)d_in[7];
    const float* wv = (const float*)d_in[8];
    const float* bv = (const float*)d_in[9];
    const float* wo = (const float*)d_in[10];
    const float* bo = (const float*)d_in[11];
    float* out = (float*)d_out;

    void *p_xn, *p_qkv, *p_ctx, *p_w, *p_bqkv;
    cudaGetSymbolAddress(&p_xn,  g_xn16);
    cudaGetSymbolAddress(&p_qkv, g_qkv16);
    cudaGetSymbolAddress(&p_ctx, g_ctx16);
    cudaGetSymbolAddress(&p_w,   g_w16);
    cudaGetSymbolAddress(&p_bqkv, g_bqkv);
    __nv_bfloat16* xn  = (__nv_bfloat16*)p_xn;
    __nv_bfloat16* qkv = (__nv_bfloat16*)p_qkv;
    __nv_bfloat16* ctx = (__nv_bfloat16*)p_ctx;
    __nv_bfloat16* w16 = (__nv_bfloat16*)p_w;
    float* bqkv = (float*)p_bqkv;

    // 0. Prep: bf16 weights, concat qkv bias
    wprep_kernel<<<4 * DD * DD / 4 / 256, 256>>>(wq, wk, wv, wo, w16);
    bprep_kernel<<<3 * DD / 256, 256>>>(bq, bk, bv, bqkv);

    // 1. LayerNorm (bf16 output)
    ln_kernel<<<ROWS, 256>>>(hidden, gamma, beta, xn);

    // 2. Fused QKV projection: [4096,1024] @ [3072,1024]^T -> bf16
    cudaFuncSetAttribute(gemm_mma<true>,
                         cudaFuncAttributeMaxDynamicSharedMemorySize, GSMEM_BYTES);
    cudaFuncSetAttribute(gemm_mma<false>,
                         cudaFuncAttributeMaxDynamicSharedMemorySize, GSMEM_BYTES);
    gemm_mma<true><<<dim3(3 * DD / 128, ROWS / 128), 256, GSMEM_BYTES>>>(
        (const uint32_t*)xn, (const uint32_t*)w16, bqkv, nullptr, qkv, 3 * DD);

    // 3. bf16 tensor-core flash attention (double-buffered, trans-V)
    int smem = ASMEM_WORDS * 4;
    cudaFuncSetAttribute(attn_mma, cudaFuncAttributeMaxDynamicSharedMemorySize, smem);
    attn_mma<<<dim3(SS / 128, HH, BB), 256, smem>>>(mask);

    // 4. Output projection + bias + residual (fp32 out)
    gemm_mma<false><<<dim3(DD / 128, ROWS / 128), 256, GSMEM_BYTES>>>(
        (const uint32_t*)ctx, (const uint32_t*)(w16 + (size_t)3 * DD * DD),
        bo, hidden, out, DD);
}